// round 10
// baseline (speedup 1.0000x reference)
#include <cuda_runtime.h>
#include <cuda_bf16.h>
#include <cstdint>

#define NTOT 32768
#define DDIM 256
#define KDIM 512
#define FIVED 1280

// ---------------- device scratch ----------------
__device__ float g_levH[(NTOT - 1) * DDIM];
__device__ float g_levC[(NTOT - 1) * DDIM];
__device__ float g_Z[16384 * FIVED];
__device__ __nv_bfloat16 g_WtHiM[FIVED * KDIM];
__device__ __nv_bfloat16 g_WtLoM[FIVED * KDIM];
__device__ __nv_bfloat16 g_WtHiS[FIVED * KDIM];
__device__ __nv_bfloat16 g_WtLoS[FIVED * KDIM];
// bf16 hi/lo mirrors of every h that feeds a GEMM A-operand
__device__ __nv_bfloat16 g_botHhi[NTOT * DDIM];
__device__ __nv_bfloat16 g_botHlo[NTOT * DDIM];
__device__ __nv_bfloat16 g_levHhi[(NTOT - 1) * DDIM];
__device__ __nv_bfloat16 g_levHlo[(NTOT - 1) * DDIM];
__device__ __nv_bfloat16 g_stHhi[NTOT * DDIM];
__device__ __nv_bfloat16 g_stHlo[NTOT * DDIM];

__device__ __forceinline__ float sigf(float x) { return 1.0f / (1.0f + __expf(-x)); }

// ---------------------------------------------------------------------------
// Weight transpose + bf16 hi/lo split: W[512,1280] -> WtHi/WtLo[1280,512]
// ---------------------------------------------------------------------------
__global__ void transpose_w(const float* __restrict__ W,
                            __nv_bfloat16* __restrict__ WtHi,
                            __nv_bfloat16* __restrict__ WtLo) {
    __shared__ float t[32][33];
    int bx = blockIdx.x * 32;   // n
    int by = blockIdx.y * 32;   // k
    int x = threadIdx.x, y = threadIdx.y;
#pragma unroll
    for (int i = 0; i < 32; i += 8)
        t[y + i][x] = W[(size_t)(by + y + i) * FIVED + bx + x];
    __syncthreads();
#pragma unroll
    for (int i = 0; i < 32; i += 8) {
        float v = t[x][y + i];
        __nv_bfloat16 hi = __float2bfloat16(v);
        __nv_bfloat16 lo = __float2bfloat16(v - __bfloat162float(hi));
        WtHi[(size_t)(bx + y + i) * KDIM + by + x] = hi;
        WtLo[(size_t)(bx + y + i) * KDIM + by + x] = lo;
    }
}

// h_bot -> bf16 hi/lo mirror
__global__ void split_bot(const float* __restrict__ h,
                          __nv_bfloat16* __restrict__ hhi,
                          __nv_bfloat16* __restrict__ hlo) {
    size_t i = (size_t)blockIdx.x * 256 + threadIdx.x;
    float v = h[i];
    __nv_bfloat16 a = __float2bfloat16(v);
    hhi[i] = a;
    hlo[i] = __float2bfloat16(v - __bfloat162float(a));
}

// ---------------- mma.sync helpers ----------------
__device__ __forceinline__ uint32_t smem_addr(const void* p) {
    return (uint32_t)__cvta_generic_to_shared(p);
}
__device__ __forceinline__ void ldm_x4(uint32_t r[4], uint32_t addr) {
    asm volatile("ldmatrix.sync.aligned.m8n8.x4.shared.b16 {%0,%1,%2,%3}, [%4];"
                 : "=r"(r[0]), "=r"(r[1]), "=r"(r[2]), "=r"(r[3]) : "r"(addr));
}
__device__ __forceinline__ void mma16816(float d[4], const uint32_t a[4],
                                         uint32_t b0, uint32_t b1) {
    asm volatile(
        "mma.sync.aligned.m16n8k16.row.col.f32.bf16.bf16.f32 "
        "{%0,%1,%2,%3}, {%4,%5,%6,%7}, {%8,%9}, {%0,%1,%2,%3};"
        : "+f"(d[0]), "+f"(d[1]), "+f"(d[2]), "+f"(d[3])
        : "r"(a[0]), "r"(a[1]), "r"(a[2]), "r"(a[3]), "r"(b0), "r"(b1));
}
__device__ __forceinline__ void cp16(void* dst, const void* src) {
    asm volatile("cp.async.cg.shared.global [%0], [%1], 16;"
                 :: "r"(smem_addr(dst)), "l"(src));
}
#define CP_COMMIT() asm volatile("cp.async.commit_group;" ::: "memory")
#define CP_WAIT(n)  asm volatile("cp.async.wait_group %0;" :: "n"(n) : "memory")

// SMEM row stride in bf16 elements (32 data + 8 pad = 80B rows)
#define ROWE 40
// per-stage tile size (elems) and offsets
#define TSZ (128 * ROWE)
#define OFF_AH 0
#define OFF_AL TSZ
#define OFF_BH (2 * TSZ)
#define OFF_BL (3 * TSZ)
#define STAGE_SZ (4 * TSZ)
#define SMEM_TOTAL (2 * STAGE_SZ * 2)   // bytes: 2 stages * 4 tiles * 10240B

// ---------------------------------------------------------------------------
// GEMM: Z[m, 0:1280] = concat(Lrow(m), Rrow(m)) @ W  via bf16x3 mma.sync
// A operands are preconverted bf16 hi/lo arrays (stride = els/ers elems).
// mode 0 (merge): Lrow = 2m, Rrow = 2m+1 (both in prev-level arrays)
// mode 1 (sum):   a=m>>k, r=m&((1<<k)-1), t=(a<<(k+1))|(1<<k)|r;
//                 Lrow = t-1 (state arrays), Rrow = (t>>k)-1 (level-k arrays)
// CTA tile 128x128, 8 warps (4M x 2N), K chunks of 32, cp.async double-buffer.
// ---------------------------------------------------------------------------
__global__ void __launch_bounds__(256) mma_gemm(
    const __nv_bfloat16* __restrict__ LHi, const __nv_bfloat16* __restrict__ LLo, int ls,
    const __nv_bfloat16* __restrict__ RHi, const __nv_bfloat16* __restrict__ RLo, int rs,
    const __nv_bfloat16* __restrict__ BHi, const __nv_bfloat16* __restrict__ BLo,
    float* __restrict__ Z, int M, int mode, int k)
{
    extern __shared__ __align__(16) __nv_bfloat16 sm[];

    const int tid = threadIdx.x;
    const int wid = tid >> 5;
    const int lane = tid & 31;
    const int warpM = wid & 3;
    const int warpN = wid >> 2;
    const int bm = blockIdx.y * 128;
    const int bn = blockIdx.x * 128;

    // ---- load geometry: one row per thread-pair, 16 K-elems per thread ----
    const int row2 = tid >> 1;        // 0..127
    const int half = tid & 1;
    int g = bm + row2;
    if (g >= M) g = 0;
    int lr, rr;
    const int mask = (1 << k) - 1;
    if (mode == 0) { lr = 2 * g; rr = 2 * g + 1; }
    else {
        int a = g >> k;
        int r = g & mask;
        int t = (a << (k + 1)) | (1 << k) | r;
        lr = t - 1;
        rr = (t >> k) - 1;
    }
    const __nv_bfloat16* LHr = LHi + (size_t)lr * ls + half * 16;
    const __nv_bfloat16* LLr = LLo + (size_t)lr * ls + half * 16;
    const __nv_bfloat16* RHr = RHi + (size_t)rr * rs + half * 16;
    const __nv_bfloat16* RLr = RLo + (size_t)rr * rs + half * 16;
    const size_t bRow = (size_t)(bn + row2) * KDIM + half * 16;
    const int dstOff = row2 * ROWE + half * 16;

    // ---- ldmatrix source coords ----
    const int aRowL = warpM * 32 + (lane & 15);
    const int aKL = (lane >> 4) << 3;
    const int bRowL = warpN * 64 + ((lane >> 4) << 3) + (lane & 7);
    const int bKL = ((lane >> 3) & 1) << 3;

    float acc[2][8][4];
#pragma unroll
    for (int mf = 0; mf < 2; mf++)
#pragma unroll
        for (int nf = 0; nf < 8; nf++)
#pragma unroll
            for (int j = 0; j < 4; j++) acc[mf][nf][j] = 0.0f;

    // ---- async fill of one chunk into stage s ----
    auto issue = [&](int c, int s) {
        const int k0 = c * 32;
        __nv_bfloat16* st = sm + s * STAGE_SZ;
        const __nv_bfloat16* ah;
        const __nv_bfloat16* al;
        if (k0 < 256) { ah = LHr + k0; al = LLr + k0; }
        else          { ah = RHr + (k0 - 256); al = RLr + (k0 - 256); }
        cp16(st + OFF_AH + dstOff, ah);
        cp16(st + OFF_AH + dstOff + 8, ah + 8);
        cp16(st + OFF_AL + dstOff, al);
        cp16(st + OFF_AL + dstOff + 8, al + 8);
        const __nv_bfloat16* bh = BHi + bRow + k0;
        const __nv_bfloat16* bl = BLo + bRow + k0;
        cp16(st + OFF_BH + dstOff, bh);
        cp16(st + OFF_BH + dstOff + 8, bh + 8);
        cp16(st + OFF_BL + dstOff, bl);
        cp16(st + OFF_BL + dstOff + 8, bl + 8);
    };

    issue(0, 0);
    CP_COMMIT();

#pragma unroll 1
    for (int c = 0; c < 16; c++) {
        if (c + 1 < 16) {
            issue(c + 1, (c + 1) & 1);
            CP_COMMIT();
            CP_WAIT(1);
        } else {
            CP_WAIT(0);
        }
        __syncthreads();

        const __nv_bfloat16* st = sm + (c & 1) * STAGE_SZ;
        const __nv_bfloat16* Ah = st + OFF_AH;
        const __nv_bfloat16* Al = st + OFF_AL;
        const __nv_bfloat16* Bh = st + OFF_BH;
        const __nv_bfloat16* Bl = st + OFF_BL;

#pragma unroll
        for (int kk = 0; kk < 32; kk += 16) {
            uint32_t ah[2][4], al[2][4];
#pragma unroll
            for (int mf = 0; mf < 2; mf++) {
                const int r = aRowL + mf * 16;
                const int kb = kk + aKL;
                ldm_x4(ah[mf], smem_addr(Ah + r * ROWE + kb));
                ldm_x4(al[mf], smem_addr(Al + r * ROWE + kb));
            }
#pragma unroll
            for (int nfp = 0; nfp < 4; nfp++) {
                uint32_t bh[4], bl[4];
                const int nr = bRowL + nfp * 16;
                const int kb = kk + bKL;
                ldm_x4(bh, smem_addr(Bh + nr * ROWE + kb));
                ldm_x4(bl, smem_addr(Bl + nr * ROWE + kb));
#pragma unroll
                for (int mf = 0; mf < 2; mf++) {
#pragma unroll
                    for (int j = 0; j < 2; j++) {
                        float* d = acc[mf][nfp * 2 + j];
                        mma16816(d, ah[mf], bh[2 * j], bh[2 * j + 1]);
                        mma16816(d, ah[mf], bl[2 * j], bl[2 * j + 1]);
                        mma16816(d, al[mf], bh[2 * j], bh[2 * j + 1]);
                    }
                }
            }
        }
        __syncthreads();
    }

    // ---- epilogue ----
#pragma unroll
    for (int mf = 0; mf < 2; mf++) {
        const int r0 = bm + warpM * 32 + mf * 16 + (lane >> 2);
#pragma unroll
        for (int nf = 0; nf < 8; nf++) {
            const int cc = bn + warpN * 64 + nf * 8 + (lane & 3) * 2;
            float* p = Z + (size_t)r0 * FIVED + cc;
            if (r0 < M) {
                p[0] = acc[mf][nf][0];
                p[1] = acc[mf][nf][1];
            }
            if (r0 + 8 < M) {
                float* q = p + 8 * FIVED;
                q[0] = acc[mf][nf][2];
                q[1] = acc[mf][nf][3];
            }
        }
    }
}

// ---------------------------------------------------------------------------
// Pointwise merge cell (+ bf16 hi/lo mirror of h for next GEMM)
// ---------------------------------------------------------------------------
__global__ void pw_merge(const float* __restrict__ Z, const float* __restrict__ b,
                         const float* __restrict__ prevC,
                         float* __restrict__ curH, float* __restrict__ curC,
                         __nv_bfloat16* __restrict__ curHhi,
                         __nv_bfloat16* __restrict__ curHlo)
{
    const int m = blockIdx.x;
    const int j = threadIdx.x;
    const float* z = Z + (size_t)m * FIVED;
    float gi = z[j] + b[j];
    float go = z[256 + j] + b[256 + j];
    float gu = z[512 + j] + b[512 + j];
    float gfl = z[768 + j] + b[768 + j];
    float gfr = z[1024 + j] + b[1024 + j];
    float cl = prevC[(size_t)(2 * m) * DDIM + j];
    float cr = prevC[(size_t)(2 * m + 1) * DDIM + j];
    float c = sigf(gi) * tanhf(gu) + sigf(gfl) * cl + sigf(gfr) * cr;
    float h = sigf(go) * tanhf(c);
    curH[(size_t)m * DDIM + j] = h;
    curC[(size_t)m * DDIM + j] = c;
    __nv_bfloat16 hh = __float2bfloat16(h);
    curHhi[(size_t)m * DDIM + j] = hh;
    curHlo[(size_t)m * DDIM + j] = __float2bfloat16(h - __bfloat162float(hh));
}

// ---------------------------------------------------------------------------
// Pointwise fenwick-step cell (+ bf16 hi/lo mirror of state h)
// ---------------------------------------------------------------------------
__global__ void pw_sum(const float* __restrict__ Z, const float* __restrict__ b,
                       const float* __restrict__ nodeH, const float* __restrict__ nodeC,
                       float* __restrict__ out,
                       __nv_bfloat16* __restrict__ stHhi,
                       __nv_bfloat16* __restrict__ stHlo, int k)
{
    const int m = blockIdx.x;
    const int j = threadIdx.x;
    const int mask = (1 << k) - 1;
    const int a = m >> k;
    const int r = m & mask;
    const int t = (a << (k + 1)) | (1 << k) | r;
    const int row = t - 1;
    const int idx = (t >> k) - 1;

    float h, c;
    if (r == 0) {
        h = nodeH[(size_t)idx * DDIM + j];
        c = nodeC[(size_t)idx * DDIM + j];
    } else {
        const float* z = Z + (size_t)m * FIVED;
        float gi = z[j] + b[j];
        float go = z[256 + j] + b[256 + j];
        float gu = z[512 + j] + b[512 + j];
        float gfl = z[768 + j] + b[768 + j];
        float gfr = z[1024 + j] + b[1024 + j];
        float cl = out[(size_t)row * 512 + 256 + j];
        float cr = nodeC[(size_t)idx * DDIM + j];
        c = sigf(gi) * tanhf(gu) + sigf(gfl) * cl + sigf(gfr) * cr;
        h = sigf(go) * tanhf(c);
    }
    out[(size_t)row * 512 + j] = h;
    out[(size_t)row * 512 + 256 + j] = c;
    __nv_bfloat16 hh = __float2bfloat16(h);
    stHhi[(size_t)row * DDIM + j] = hh;
    stHlo[(size_t)row * DDIM + j] = __float2bfloat16(h - __bfloat162float(hh));
}

static inline int lev_off(int k) { return NTOT - (NTOT >> (k - 1)); }

extern "C" void kernel_launch(void* const* d_in, const int* in_sizes, int n_in,
                              void* d_out, int out_size)
{
    const float* h_bot = (const float*)d_in[0];
    const float* c_bot = (const float*)d_in[1];
    const float* W_merge = (const float*)d_in[2];
    const float* b_merge = (const float*)d_in[3];
    const float* W_sum = (const float*)d_in[4];
    const float* b_sum = (const float*)d_in[5];
    float* out = (float*)d_out;

    float *levH, *levC, *Z;
    __nv_bfloat16 *WtHiM, *WtLoM, *WtHiS, *WtLoS;
    __nv_bfloat16 *botHhi, *botHlo, *levHhi, *levHlo, *stHhi, *stHlo;
    cudaGetSymbolAddress((void**)&levH, g_levH);
    cudaGetSymbolAddress((void**)&levC, g_levC);
    cudaGetSymbolAddress((void**)&Z, g_Z);
    cudaGetSymbolAddress((void**)&WtHiM, g_WtHiM);
    cudaGetSymbolAddress((void**)&WtLoM, g_WtLoM);
    cudaGetSymbolAddress((void**)&WtHiS, g_WtHiS);
    cudaGetSymbolAddress((void**)&WtLoS, g_WtLoS);
    cudaGetSymbolAddress((void**)&botHhi, g_botHhi);
    cudaGetSymbolAddress((void**)&botHlo, g_botHlo);
    cudaGetSymbolAddress((void**)&levHhi, g_levHhi);
    cudaGetSymbolAddress((void**)&levHlo, g_levHlo);
    cudaGetSymbolAddress((void**)&stHhi, g_stHhi);
    cudaGetSymbolAddress((void**)&stHlo, g_stHlo);

    cudaFuncSetAttribute(mma_gemm, cudaFuncAttributeMaxDynamicSharedMemorySize, SMEM_TOTAL);

    transpose_w<<<dim3(FIVED / 32, KDIM / 32), dim3(32, 8)>>>(W_merge, WtHiM, WtLoM);
    transpose_w<<<dim3(FIVED / 32, KDIM / 32), dim3(32, 8)>>>(W_sum, WtHiS, WtLoS);
    split_bot<<<NTOT, 256>>>(h_bot, botHhi, botHlo);

    // ---- Phase 1: build levels 1..15 ----
    for (int k = 1; k <= 15; k++) {
        int Mrows = NTOT >> k;
        const __nv_bfloat16* pHhi = (k == 1) ? botHhi : (levHhi + (size_t)lev_off(k - 1) * DDIM);
        const __nv_bfloat16* pHlo = (k == 1) ? botHlo : (levHlo + (size_t)lev_off(k - 1) * DDIM);
        const float* prevC = (k == 1) ? c_bot : (levC + (size_t)lev_off(k - 1) * DDIM);
        float* curH = levH + (size_t)lev_off(k) * DDIM;
        float* curC = levC + (size_t)lev_off(k) * DDIM;
        __nv_bfloat16* cHhi = levHhi + (size_t)lev_off(k) * DDIM;
        __nv_bfloat16* cHlo = levHlo + (size_t)lev_off(k) * DDIM;

        dim3 grid(FIVED / 128, (Mrows + 127) / 128);
        mma_gemm<<<grid, 256, SMEM_TOTAL>>>(pHhi, pHlo, DDIM, pHhi, pHlo, DDIM,
                                            WtHiM, WtLoM, Z, Mrows, 0, 0);
        pw_merge<<<Mrows, 256>>>(Z, b_merge, prevC, curH, curC, cHhi, cHlo);
    }

    // ---- Phase 2: fenwick prefix combine ----
    pw_sum<<<NTOT / 2, 256>>>(Z, b_sum, h_bot, c_bot, out, stHhi, stHlo, 0);

    for (int k = 1; k <= 14; k++) {
        const float* nodeH = levH + (size_t)lev_off(k) * DDIM;
        const float* nodeC = levC + (size_t)lev_off(k) * DDIM;
        const __nv_bfloat16* nHhi = levHhi + (size_t)lev_off(k) * DDIM;
        const __nv_bfloat16* nHlo = levHlo + (size_t)lev_off(k) * DDIM;
        dim3 grid(FIVED / 128, (NTOT / 2 + 127) / 128);
        mma_gemm<<<grid, 256, SMEM_TOTAL>>>(stHhi, stHlo, DDIM, nHhi, nHlo, DDIM,
                                            WtHiS, WtLoS, Z, NTOT / 2, 1, k);
        pw_sum<<<NTOT / 2, 256>>>(Z, b_sum, nodeH, nodeC, out, stHhi, stHlo, k);
    }

    {
        const float* nodeH = levH + (size_t)lev_off(15) * DDIM;
        const float* nodeC = levC + (size_t)lev_off(15) * DDIM;
        pw_sum<<<1, 256>>>(Z, b_sum, nodeH, nodeC, out, stHhi, stHlo, 15);
    }
}

// round 13
// speedup vs baseline: 1.6753x; 1.6753x over previous
#include <cuda_runtime.h>
#include <cuda_bf16.h>
#include <cstdint>

#define NTOT 32768
#define DDIM 256
#define KDIM 512
#define FIVED 1280

// ---------------- device scratch ----------------
__device__ float g_levH[(NTOT - 1) * DDIM];
__device__ float g_levC[(NTOT - 1) * DDIM];
__device__ float g_Z[16384 * FIVED];
__device__ float g_ZN[(NTOT - 1) * FIVED];     // precomputed node-half gate preact
__device__ __nv_bfloat16 g_WtHiM[FIVED * KDIM];
__device__ __nv_bfloat16 g_WtLoM[FIVED * KDIM];
__device__ __nv_bfloat16 g_WtHiS[FIVED * KDIM];
__device__ __nv_bfloat16 g_WtLoS[FIVED * KDIM];
// bf16 hi/lo mirrors of every h that feeds a GEMM A-operand
__device__ __nv_bfloat16 g_botHhi[NTOT * DDIM];
__device__ __nv_bfloat16 g_botHlo[NTOT * DDIM];
__device__ __nv_bfloat16 g_levHhi[(NTOT - 1) * DDIM];
__device__ __nv_bfloat16 g_levHlo[(NTOT - 1) * DDIM];
__device__ __nv_bfloat16 g_stHhi[NTOT * DDIM];
__device__ __nv_bfloat16 g_stHlo[NTOT * DDIM];

__device__ __forceinline__ float sigf(float x) { return 1.0f / (1.0f + __expf(-x)); }

// ---------------------------------------------------------------------------
// Weight transpose + bf16 hi/lo split: W[512,1280] -> WtHi/WtLo[1280,512]
// ---------------------------------------------------------------------------
__global__ void transpose_w(const float* __restrict__ W,
                            __nv_bfloat16* __restrict__ WtHi,
                            __nv_bfloat16* __restrict__ WtLo) {
    __shared__ float t[32][33];
    int bx = blockIdx.x * 32;   // n
    int by = blockIdx.y * 32;   // k
    int x = threadIdx.x, y = threadIdx.y;
#pragma unroll
    for (int i = 0; i < 32; i += 8)
        t[y + i][x] = W[(size_t)(by + y + i) * FIVED + bx + x];
    __syncthreads();
#pragma unroll
    for (int i = 0; i < 32; i += 8) {
        float v = t[x][y + i];
        __nv_bfloat16 hi = __float2bfloat16(v);
        __nv_bfloat16 lo = __float2bfloat16(v - __bfloat162float(hi));
        WtHi[(size_t)(bx + y + i) * KDIM + by + x] = hi;
        WtLo[(size_t)(bx + y + i) * KDIM + by + x] = lo;
    }
}

// h_bot -> bf16 hi/lo mirror
__global__ void split_bot(const float* __restrict__ h,
                          __nv_bfloat16* __restrict__ hhi,
                          __nv_bfloat16* __restrict__ hlo) {
    size_t i = (size_t)blockIdx.x * 256 + threadIdx.x;
    float v = h[i];
    __nv_bfloat16 a = __float2bfloat16(v);
    hhi[i] = a;
    hlo[i] = __float2bfloat16(v - __bfloat162float(a));
}

// ---------------- mma.sync helpers ----------------
__device__ __forceinline__ uint32_t smem_addr(const void* p) {
    return (uint32_t)__cvta_generic_to_shared(p);
}
__device__ __forceinline__ void ldm_x4(uint32_t r[4], uint32_t addr) {
    asm volatile("ldmatrix.sync.aligned.m8n8.x4.shared.b16 {%0,%1,%2,%3}, [%4];"
                 : "=r"(r[0]), "=r"(r[1]), "=r"(r[2]), "=r"(r[3]) : "r"(addr));
}
__device__ __forceinline__ void mma16816(float d[4], const uint32_t a[4],
                                         uint32_t b0, uint32_t b1) {
    asm volatile(
        "mma.sync.aligned.m16n8k16.row.col.f32.bf16.bf16.f32 "
        "{%0,%1,%2,%3}, {%4,%5,%6,%7}, {%8,%9}, {%0,%1,%2,%3};"
        : "+f"(d[0]), "+f"(d[1]), "+f"(d[2]), "+f"(d[3])
        : "r"(a[0]), "r"(a[1]), "r"(a[2]), "r"(a[3]), "r"(b0), "r"(b1));
}
__device__ __forceinline__ void cp16(void* dst, const void* src) {
    asm volatile("cp.async.cg.shared.global [%0], [%1], 16;"
                 :: "r"(smem_addr(dst)), "l"(src));
}
#define CP_COMMIT() asm volatile("cp.async.commit_group;" ::: "memory")
#define CP_WAIT(n)  asm volatile("cp.async.wait_group %0;" :: "n"(n) : "memory")

// SMEM row stride in bf16 elements (32 data + 8 pad = 80B rows)
#define ROWE 40
#define TSZ (128 * ROWE)
#define OFF_AH 0
#define OFF_AL TSZ
#define OFF_BH (2 * TSZ)
#define OFF_BL (3 * TSZ)
#define STAGE_SZ (4 * TSZ)
#define SMEM_TOTAL (2 * STAGE_SZ * 2)   // bytes

// ---------------------------------------------------------------------------
// GEMM (bf16x3 mma.sync): Z[m, bnCols] = Arow(m) @ Wt-slice
// mode 0 (merge, kChunks=16): Arow = concat(LHi[2m], LHi[2m+1]) (K=512)
// mode 1 (fenwick state, kChunks=8): Arow = L[t-1] (K=256)
// mode 2 (identity, kChunks=8): Arow = L[m] (K=256)
// bOff selects the Wt column window (0 = first 256 K, 256 = second).
// CTA tile 128x128, 8 warps (4M x 2N), K chunks of 32, cp.async double-buffer.
// Inner loop issues MMAs in 3 passes of 16 independent ops (no acc chains).
// ---------------------------------------------------------------------------
__global__ void __launch_bounds__(256) mma_gemm(
    const __nv_bfloat16* __restrict__ LHi, const __nv_bfloat16* __restrict__ LLo, int ls,
    const __nv_bfloat16* __restrict__ BHi, const __nv_bfloat16* __restrict__ BLo, int bOff,
    float* __restrict__ Z, int M, int mode, int k, int kChunks)
{
    extern __shared__ __align__(16) __nv_bfloat16 sm[];

    const int tid = threadIdx.x;
    const int wid = tid >> 5;
    const int lane = tid & 31;
    const int warpM = wid & 3;
    const int warpN = wid >> 2;
    const int bm = blockIdx.y * 128;
    const int bn = blockIdx.x * 128;

    // ---- load geometry: one row per thread-pair, 16 K-elems per thread ----
    const int row2 = tid >> 1;        // 0..127
    const int half = tid & 1;
    int g = bm + row2;
    if (g >= M) g = 0;
    int lr, rr;
    const int mask = (1 << k) - 1;
    if (mode == 0) { lr = 2 * g; rr = 2 * g + 1; }
    else if (mode == 1) {
        int a = g >> k;
        int r = g & mask;
        int t = (a << (k + 1)) | (1 << k) | r;
        lr = t - 1;
        rr = lr;
    } else { lr = g; rr = g; }
    const __nv_bfloat16* LHr = LHi + (size_t)lr * ls + half * 16;
    const __nv_bfloat16* LLr = LLo + (size_t)lr * ls + half * 16;
    const __nv_bfloat16* RHr = LHi + (size_t)rr * ls + half * 16;
    const __nv_bfloat16* RLr = LLo + (size_t)rr * ls + half * 16;
    const size_t bRow = (size_t)(bn + row2) * KDIM + bOff + half * 16;
    const int dstOff = row2 * ROWE + half * 16;

    // ---- ldmatrix source coords ----
    const int aRowL = warpM * 32 + (lane & 15);
    const int aKL = (lane >> 4) << 3;
    const int bRowL = warpN * 64 + ((lane >> 4) << 3) + (lane & 7);
    const int bKL = ((lane >> 3) & 1) << 3;

    float acc[2][8][4];
#pragma unroll
    for (int mf = 0; mf < 2; mf++)
#pragma unroll
        for (int nf = 0; nf < 8; nf++)
#pragma unroll
            for (int j = 0; j < 4; j++) acc[mf][nf][j] = 0.0f;

    auto issue = [&](int c, int s) {
        const int k0 = c * 32;
        __nv_bfloat16* st = sm + s * STAGE_SZ;
        const __nv_bfloat16* ah;
        const __nv_bfloat16* al;
        if (k0 < 256) { ah = LHr + k0; al = LLr + k0; }
        else          { ah = RHr + (k0 - 256); al = RLr + (k0 - 256); }
        cp16(st + OFF_AH + dstOff, ah);
        cp16(st + OFF_AH + dstOff + 8, ah + 8);
        cp16(st + OFF_AL + dstOff, al);
        cp16(st + OFF_AL + dstOff + 8, al + 8);
        const __nv_bfloat16* bh = BHi + bRow + k0;
        const __nv_bfloat16* bl = BLo + bRow + k0;
        cp16(st + OFF_BH + dstOff, bh);
        cp16(st + OFF_BH + dstOff + 8, bh + 8);
        cp16(st + OFF_BL + dstOff, bl);
        cp16(st + OFF_BL + dstOff + 8, bl + 8);
    };

    issue(0, 0);
    CP_COMMIT();

#pragma unroll 1
    for (int c = 0; c < kChunks; c++) {
        if (c + 1 < kChunks) {
            issue(c + 1, (c + 1) & 1);
            CP_COMMIT();
            CP_WAIT(1);
        } else {
            CP_WAIT(0);
        }
        __syncthreads();

        const __nv_bfloat16* st = sm + (c & 1) * STAGE_SZ;
        const __nv_bfloat16* Ah = st + OFF_AH;
        const __nv_bfloat16* Al = st + OFF_AL;
        const __nv_bfloat16* Bh = st + OFF_BH;
        const __nv_bfloat16* Bl = st + OFF_BL;

#pragma unroll
        for (int kk = 0; kk < 32; kk += 16) {
            // ---- load all fragments for this k16 step ----
            uint32_t ah[2][4], al[2][4];
#pragma unroll
            for (int mf = 0; mf < 2; mf++) {
                const int r = aRowL + mf * 16;
                const int kb = kk + aKL;
                ldm_x4(ah[mf], smem_addr(Ah + r * ROWE + kb));
                ldm_x4(al[mf], smem_addr(Al + r * ROWE + kb));
            }
            uint32_t bh[4][4], bl[4][4];
#pragma unroll
            for (int nfp = 0; nfp < 4; nfp++) {
                const int nr = bRowL + nfp * 16;
                const int kb = kk + bKL;
                ldm_x4(bh[nfp], smem_addr(Bh + nr * ROWE + kb));
                ldm_x4(bl[nfp], smem_addr(Bl + nr * ROWE + kb));
            }
            // ---- 3 passes of 16 independent MMAs (no same-acc chains) ----
#pragma unroll
            for (int mf = 0; mf < 2; mf++)
#pragma unroll
                for (int nfp = 0; nfp < 4; nfp++)
#pragma unroll
                    for (int j = 0; j < 2; j++)
                        mma16816(acc[mf][nfp * 2 + j], ah[mf],
                                 bh[nfp][2 * j], bh[nfp][2 * j + 1]);
#pragma unroll
            for (int mf = 0; mf < 2; mf++)
#pragma unroll
                for (int nfp = 0; nfp < 4; nfp++)
#pragma unroll
                    for (int j = 0; j < 2; j++)
                        mma16816(acc[mf][nfp * 2 + j], ah[mf],
                                 bl[nfp][2 * j], bl[nfp][2 * j + 1]);
#pragma unroll
            for (int mf = 0; mf < 2; mf++)
#pragma unroll
                for (int nfp = 0; nfp < 4; nfp++)
#pragma unroll
                    for (int j = 0; j < 2; j++)
                        mma16816(acc[mf][nfp * 2 + j], al[mf],
                                 bh[nfp][2 * j], bh[nfp][2 * j + 1]);
        }
        __syncthreads();
    }

    // ---- epilogue ----
#pragma unroll
    for (int mf = 0; mf < 2; mf++) {
        const int r0 = bm + warpM * 32 + mf * 16 + (lane >> 2);
#pragma unroll
        for (int nf = 0; nf < 8; nf++) {
            const int cc = bn + warpN * 64 + nf * 8 + (lane & 3) * 2;
            float* p = Z + (size_t)r0 * FIVED + cc;
            if (r0 < M) {
                p[0] = acc[mf][nf][0];
                p[1] = acc[mf][nf][1];
            }
            if (r0 + 8 < M) {
                float* q = p + 8 * FIVED;
                q[0] = acc[mf][nf][2];
                q[1] = acc[mf][nf][3];
            }
        }
    }
}

// ---------------------------------------------------------------------------
// Pointwise merge cell (+ bf16 hi/lo mirror of h)
// ---------------------------------------------------------------------------
__global__ void pw_merge(const float* __restrict__ Z, const float* __restrict__ b,
                         const float* __restrict__ prevC,
                         float* __restrict__ curH, float* __restrict__ curC,
                         __nv_bfloat16* __restrict__ curHhi,
                         __nv_bfloat16* __restrict__ curHlo)
{
    const int m = blockIdx.x;
    const int j = threadIdx.x;
    const float* z = Z + (size_t)m * FIVED;
    float gi = z[j] + b[j];
    float go = z[256 + j] + b[256 + j];
    float gu = z[512 + j] + b[512 + j];
    float gfl = z[768 + j] + b[768 + j];
    float gfr = z[1024 + j] + b[1024 + j];
    float cl = prevC[(size_t)(2 * m) * DDIM + j];
    float cr = prevC[(size_t)(2 * m + 1) * DDIM + j];
    float c = sigf(gi) * tanhf(gu) + sigf(gfl) * cl + sigf(gfr) * cr;
    float h = sigf(go) * tanhf(c);
    curH[(size_t)m * DDIM + j] = h;
    curC[(size_t)m * DDIM + j] = c;
    __nv_bfloat16 hh = __float2bfloat16(h);
    curHhi[(size_t)m * DDIM + j] = hh;
    curHlo[(size_t)m * DDIM + j] = __float2bfloat16(h - __bfloat162float(hh));
}

// ---------------------------------------------------------------------------
// Pointwise fenwick-step cell: z = zL (per-step) + zN (precomputed node) + b
// ---------------------------------------------------------------------------
__global__ void pw_sum(const float* __restrict__ ZL, const float* __restrict__ ZNk,
                       const float* __restrict__ b,
                       const float* __restrict__ nodeH, const float* __restrict__ nodeC,
                       float* __restrict__ out,
                       __nv_bfloat16* __restrict__ stHhi,
                       __nv_bfloat16* __restrict__ stHlo, int k)
{
    const int m = blockIdx.x;
    const int j = threadIdx.x;
    const int mask = (1 << k) - 1;
    const int a = m >> k;
    const int r = m & mask;
    const int t = (a << (k + 1)) | (1 << k) | r;
    const int row = t - 1;
    const int idx = (t >> k) - 1;

    float h, c;
    if (r == 0) {
        h = nodeH[(size_t)idx * DDIM + j];
        c = nodeC[(size_t)idx * DDIM + j];
    } else {
        const float* zl = ZL + (size_t)m * FIVED;
        const float* zn = ZNk + (size_t)idx * FIVED;
        float gi = zl[j] + zn[j] + b[j];
        float go = zl[256 + j] + zn[256 + j] + b[256 + j];
        float gu = zl[512 + j] + zn[512 + j] + b[512 + j];
        float gfl = zl[768 + j] + zn[768 + j] + b[768 + j];
        float gfr = zl[1024 + j] + zn[1024 + j] + b[1024 + j];
        float cl = out[(size_t)row * 512 + 256 + j];
        float cr = nodeC[(size_t)idx * DDIM + j];
        c = sigf(gi) * tanhf(gu) + sigf(gfl) * cl + sigf(gfr) * cr;
        h = sigf(go) * tanhf(c);
    }
    out[(size_t)row * 512 + j] = h;
    out[(size_t)row * 512 + 256 + j] = c;
    __nv_bfloat16 hh = __float2bfloat16(h);
    stHhi[(size_t)row * DDIM + j] = hh;
    stHlo[(size_t)row * DDIM + j] = __float2bfloat16(h - __bfloat162float(hh));
}

static inline int lev_off(int k) { return NTOT - (NTOT >> (k - 1)); }

extern "C" void kernel_launch(void* const* d_in, const int* in_sizes, int n_in,
                              void* d_out, int out_size)
{
    const float* h_bot = (const float*)d_in[0];
    const float* c_bot = (const float*)d_in[1];
    const float* W_merge = (const float*)d_in[2];
    const float* b_merge = (const float*)d_in[3];
    const float* W_sum = (const float*)d_in[4];
    const float* b_sum = (const float*)d_in[5];
    float* out = (float*)d_out;

    float *levH, *levC, *Z, *ZN;
    __nv_bfloat16 *WtHiM, *WtLoM, *WtHiS, *WtLoS;
    __nv_bfloat16 *botHhi, *botHlo, *levHhi, *levHlo, *stHhi, *stHlo;
    cudaGetSymbolAddress((void**)&levH, g_levH);
    cudaGetSymbolAddress((void**)&levC, g_levC);
    cudaGetSymbolAddress((void**)&Z, g_Z);
    cudaGetSymbolAddress((void**)&ZN, g_ZN);
    cudaGetSymbolAddress((void**)&WtHiM, g_WtHiM);
    cudaGetSymbolAddress((void**)&WtLoM, g_WtLoM);
    cudaGetSymbolAddress((void**)&WtHiS, g_WtHiS);
    cudaGetSymbolAddress((void**)&WtLoS, g_WtLoS);
    cudaGetSymbolAddress((void**)&botHhi, g_botHhi);
    cudaGetSymbolAddress((void**)&botHlo, g_botHlo);
    cudaGetSymbolAddress((void**)&levHhi, g_levHhi);
    cudaGetSymbolAddress((void**)&levHlo, g_levHlo);
    cudaGetSymbolAddress((void**)&stHhi, g_stHhi);
    cudaGetSymbolAddress((void**)&stHlo, g_stHlo);

    cudaFuncSetAttribute(mma_gemm, cudaFuncAttributeMaxDynamicSharedMemorySize, SMEM_TOTAL);

    transpose_w<<<dim3(FIVED / 32, KDIM / 32), dim3(32, 8)>>>(W_merge, WtHiM, WtLoM);
    transpose_w<<<dim3(FIVED / 32, KDIM / 32), dim3(32, 8)>>>(W_sum, WtHiS, WtLoS);
    split_bot<<<NTOT, 256>>>(h_bot, botHhi, botHlo);

    // ---- Phase 1: build levels 1..15 ----
    for (int k = 1; k <= 15; k++) {
        int Mrows = NTOT >> k;
        const __nv_bfloat16* pHhi = (k == 1) ? botHhi : (levHhi + (size_t)lev_off(k - 1) * DDIM);
        const __nv_bfloat16* pHlo = (k == 1) ? botHlo : (levHlo + (size_t)lev_off(k - 1) * DDIM);
        const float* prevC = (k == 1) ? c_bot : (levC + (size_t)lev_off(k - 1) * DDIM);
        float* curH = levH + (size_t)lev_off(k) * DDIM;
        float* curC = levC + (size_t)lev_off(k) * DDIM;
        __nv_bfloat16* cHhi = levHhi + (size_t)lev_off(k) * DDIM;
        __nv_bfloat16* cHlo = levHlo + (size_t)lev_off(k) * DDIM;

        dim3 grid(FIVED / 128, (Mrows + 127) / 128);
        mma_gemm<<<grid, 256, SMEM_TOTAL>>>(pHhi, pHlo, DDIM, WtHiM, WtLoM, 0,
                                            Z, Mrows, 0, 0, 16);
        pw_merge<<<Mrows, 256>>>(Z, b_merge, prevC, curH, curC, cHhi, cHlo);
    }

    // ---- Precompute node-half gates for ALL tree nodes (K=256, W cols 256:512) ----
    {
        dim3 grid(FIVED / 128, (NTOT - 1 + 127) / 128);
        mma_gemm<<<grid, 256, SMEM_TOTAL>>>(levHhi, levHlo, DDIM, WtHiS, WtLoS, 256,
                                            ZN, NTOT - 1, 2, 0, 8);
    }

    // ---- Phase 2: fenwick prefix combine ----
    pw_sum<<<NTOT / 2, 256>>>(Z, ZN, b_sum, h_bot, c_bot, out, stHhi, stHlo, 0);

    for (int k = 1; k <= 14; k++) {
        const float* nodeH = levH + (size_t)lev_off(k) * DDIM;
        const float* nodeC = levC + (size_t)lev_off(k) * DDIM;
        const float* ZNk = ZN + (size_t)lev_off(k) * FIVED;
        dim3 grid(FIVED / 128, (NTOT / 2 + 127) / 128);
        mma_gemm<<<grid, 256, SMEM_TOTAL>>>(stHhi, stHlo, DDIM, WtHiS, WtLoS, 0,
                                            Z, NTOT / 2, 1, k, 8);
        pw_sum<<<NTOT / 2, 256>>>(Z, ZNk, b_sum, nodeH, nodeC, out, stHhi, stHlo, k);
    }

    {
        const float* nodeH = levH + (size_t)lev_off(15) * DDIM;
        const float* nodeC = levC + (size_t)lev_off(15) * DDIM;
        pw_sum<<<1, 256>>>(Z, ZN, b_sum, nodeH, nodeC, out, stHhi, stHlo, 15);
    }
}

// round 14
// speedup vs baseline: 1.8995x; 1.1339x over previous
#include <cuda_runtime.h>
#include <cuda_bf16.h>
#include <cstdint>

#define NTOT 32768
#define DDIM 256
#define KDIM 512
#define FIVED 1280

// ---------------- device scratch ----------------
__device__ float g_levH[(NTOT - 1) * DDIM];
__device__ float g_levC[(NTOT - 1) * DDIM];
__device__ float g_Z[16384 * FIVED];
__device__ float g_ZN[(NTOT - 1) * FIVED];     // precomputed node-half gate preact
__device__ __nv_bfloat16 g_WtHiM[FIVED * KDIM];
__device__ __nv_bfloat16 g_WtLoM[FIVED * KDIM];
__device__ __nv_bfloat16 g_WtHiS[FIVED * KDIM];
__device__ __nv_bfloat16 g_WtLoS[FIVED * KDIM];
// bf16 hi/lo mirrors of every h that feeds a GEMM A-operand
__device__ __nv_bfloat16 g_botHhi[NTOT * DDIM];
__device__ __nv_bfloat16 g_botHlo[NTOT * DDIM];
__device__ __nv_bfloat16 g_levHhi[(NTOT - 1) * DDIM];
__device__ __nv_bfloat16 g_levHlo[(NTOT - 1) * DDIM];
__device__ __nv_bfloat16 g_stHhi[NTOT * DDIM];
__device__ __nv_bfloat16 g_stHlo[NTOT * DDIM];

__device__ __forceinline__ float sigf(float x) { return 1.0f / (1.0f + __expf(-x)); }

// ---------------------------------------------------------------------------
// Weight transpose + bf16 hi/lo split: W[512,1280] -> WtHi/WtLo[1280,512]
// ---------------------------------------------------------------------------
__global__ void transpose_w(const float* __restrict__ W,
                            __nv_bfloat16* __restrict__ WtHi,
                            __nv_bfloat16* __restrict__ WtLo) {
    __shared__ float t[32][33];
    int bx = blockIdx.x * 32;   // n
    int by = blockIdx.y * 32;   // k
    int x = threadIdx.x, y = threadIdx.y;
#pragma unroll
    for (int i = 0; i < 32; i += 8)
        t[y + i][x] = W[(size_t)(by + y + i) * FIVED + bx + x];
    __syncthreads();
#pragma unroll
    for (int i = 0; i < 32; i += 8) {
        float v = t[x][y + i];
        __nv_bfloat16 hi = __float2bfloat16(v);
        __nv_bfloat16 lo = __float2bfloat16(v - __bfloat162float(hi));
        WtHi[(size_t)(bx + y + i) * KDIM + by + x] = hi;
        WtLo[(size_t)(bx + y + i) * KDIM + by + x] = lo;
    }
}

// h_bot -> bf16 hi/lo mirror
__global__ void split_bot(const float* __restrict__ h,
                          __nv_bfloat16* __restrict__ hhi,
                          __nv_bfloat16* __restrict__ hlo) {
    size_t i = (size_t)blockIdx.x * 256 + threadIdx.x;
    float v = h[i];
    __nv_bfloat16 a = __float2bfloat16(v);
    hhi[i] = a;
    hlo[i] = __float2bfloat16(v - __bfloat162float(a));
}

// ---------------- mma.sync helpers ----------------
__device__ __forceinline__ uint32_t smem_addr(const void* p) {
    return (uint32_t)__cvta_generic_to_shared(p);
}
__device__ __forceinline__ void ldm_x4(uint32_t r[4], uint32_t addr) {
    asm volatile("ldmatrix.sync.aligned.m8n8.x4.shared.b16 {%0,%1,%2,%3}, [%4];"
                 : "=r"(r[0]), "=r"(r[1]), "=r"(r[2]), "=r"(r[3]) : "r"(addr));
}
__device__ __forceinline__ void mma16816(float d[4], const uint32_t a[4],
                                         uint32_t b0, uint32_t b1) {
    asm volatile(
        "mma.sync.aligned.m16n8k16.row.col.f32.bf16.bf16.f32 "
        "{%0,%1,%2,%3}, {%4,%5,%6,%7}, {%8,%9}, {%0,%1,%2,%3};"
        : "+f"(d[0]), "+f"(d[1]), "+f"(d[2]), "+f"(d[3])
        : "r"(a[0]), "r"(a[1]), "r"(a[2]), "r"(a[3]), "r"(b0), "r"(b1));
}
__device__ __forceinline__ void cp16(void* dst, const void* src) {
    asm volatile("cp.async.cg.shared.global [%0], [%1], 16;"
                 :: "r"(smem_addr(dst)), "l"(src));
}
#define CP_COMMIT() asm volatile("cp.async.commit_group;" ::: "memory")
#define CP_WAIT(n)  asm volatile("cp.async.wait_group %0;" :: "n"(n) : "memory")

// SMEM row stride in bf16 elements (32 data + 8 pad = 80B rows)
#define ROWE 40
#define TSZ (128 * ROWE)
#define OFF_AH 0
#define OFF_AL TSZ
#define OFF_BH (2 * TSZ)
#define OFF_BL (3 * TSZ)
#define STAGE_SZ (4 * TSZ)
#define SMEM_TOTAL (2 * STAGE_SZ * 2)   // bytes (80KB -> 2 CTAs/SM fit in 228KB)

// ---------------------------------------------------------------------------
// GEMM (bf16x3 mma.sync): Z[m, bnCols] = Arow(m) @ Wt-slice
// mode 0 (merge, kChunks=16): Arow = concat(LHi[2m], LHi[2m+1]) (K=512)
// mode 1 (fenwick state, kChunks=8): Arow = L[t-1] (K=256)
// mode 2 (identity, kChunks=8): Arow = L[m] (K=256)
// bOff selects the Wt column window (0 = first 256 K, 256 = second).
// CTA tile 128x128, 8 warps (4M x 2N), K chunks of 32, cp.async double-buffer.
// __launch_bounds__(256,2): cap regs at 128 so 2 CTAs/SM co-reside (the
// R13 profile showed regs=132 -> 1 CTA/SM -> occ 12.4%, tensor 41%).
// ---------------------------------------------------------------------------
__global__ void __launch_bounds__(256, 2) mma_gemm(
    const __nv_bfloat16* __restrict__ LHi, const __nv_bfloat16* __restrict__ LLo, int ls,
    const __nv_bfloat16* __restrict__ BHi, const __nv_bfloat16* __restrict__ BLo, int bOff,
    float* __restrict__ Z, int M, int mode, int k, int kChunks)
{
    extern __shared__ __align__(16) __nv_bfloat16 sm[];

    const int tid = threadIdx.x;
    const int wid = tid >> 5;
    const int lane = tid & 31;
    const int warpM = wid & 3;
    const int warpN = wid >> 2;
    const int bm = blockIdx.y * 128;
    const int bn = blockIdx.x * 128;

    // ---- load geometry: one row per thread-pair, 16 K-elems per thread ----
    const int row2 = tid >> 1;        // 0..127
    const int half = tid & 1;
    int g = bm + row2;
    if (g >= M) g = 0;
    int lr, rr;
    const int mask = (1 << k) - 1;
    if (mode == 0) { lr = 2 * g; rr = 2 * g + 1; }
    else if (mode == 1) {
        int a = g >> k;
        int r = g & mask;
        int t = (a << (k + 1)) | (1 << k) | r;
        lr = t - 1;
        rr = lr;
    } else { lr = g; rr = g; }
    const __nv_bfloat16* LHr = LHi + (size_t)lr * ls + half * 16;
    const __nv_bfloat16* LLr = LLo + (size_t)lr * ls + half * 16;
    const __nv_bfloat16* RHr = LHi + (size_t)rr * ls + half * 16;
    const __nv_bfloat16* RLr = LLo + (size_t)rr * ls + half * 16;
    const size_t bRow = (size_t)(bn + row2) * KDIM + bOff + half * 16;
    const int dstOff = row2 * ROWE + half * 16;

    // ---- ldmatrix source coords ----
    const int aRowL = warpM * 32 + (lane & 15);
    const int aKL = (lane >> 4) << 3;
    const int bRowL = warpN * 64 + ((lane >> 4) << 3) + (lane & 7);
    const int bKL = ((lane >> 3) & 1) << 3;

    float acc[2][8][4];
#pragma unroll
    for (int mf = 0; mf < 2; mf++)
#pragma unroll
        for (int nf = 0; nf < 8; nf++)
#pragma unroll
            for (int j = 0; j < 4; j++) acc[mf][nf][j] = 0.0f;

    auto issue = [&](int c, int s) {
        const int k0 = c * 32;
        __nv_bfloat16* st = sm + s * STAGE_SZ;
        const __nv_bfloat16* ah;
        const __nv_bfloat16* al;
        if (k0 < 256) { ah = LHr + k0; al = LLr + k0; }
        else          { ah = RHr + (k0 - 256); al = RLr + (k0 - 256); }
        cp16(st + OFF_AH + dstOff, ah);
        cp16(st + OFF_AH + dstOff + 8, ah + 8);
        cp16(st + OFF_AL + dstOff, al);
        cp16(st + OFF_AL + dstOff + 8, al + 8);
        const __nv_bfloat16* bh = BHi + bRow + k0;
        const __nv_bfloat16* bl = BLo + bRow + k0;
        cp16(st + OFF_BH + dstOff, bh);
        cp16(st + OFF_BH + dstOff + 8, bh + 8);
        cp16(st + OFF_BL + dstOff, bl);
        cp16(st + OFF_BL + dstOff + 8, bl + 8);
    };

    issue(0, 0);
    CP_COMMIT();

#pragma unroll 1
    for (int c = 0; c < kChunks; c++) {
        if (c + 1 < kChunks) {
            issue(c + 1, (c + 1) & 1);
            CP_COMMIT();
            CP_WAIT(1);
        } else {
            CP_WAIT(0);
        }
        __syncthreads();

        const __nv_bfloat16* st = sm + (c & 1) * STAGE_SZ;
        const __nv_bfloat16* Ah = st + OFF_AH;
        const __nv_bfloat16* Al = st + OFF_AL;
        const __nv_bfloat16* Bh = st + OFF_BH;
        const __nv_bfloat16* Bl = st + OFF_BL;

#pragma unroll
        for (int kk = 0; kk < 32; kk += 16) {
            // ---- load all fragments for this k16 step ----
            uint32_t ah[2][4], al[2][4];
#pragma unroll
            for (int mf = 0; mf < 2; mf++) {
                const int r = aRowL + mf * 16;
                const int kb = kk + aKL;
                ldm_x4(ah[mf], smem_addr(Ah + r * ROWE + kb));
                ldm_x4(al[mf], smem_addr(Al + r * ROWE + kb));
            }
            uint32_t bh[4][4], bl[4][4];
#pragma unroll
            for (int nfp = 0; nfp < 4; nfp++) {
                const int nr = bRowL + nfp * 16;
                const int kb = kk + bKL;
                ldm_x4(bh[nfp], smem_addr(Bh + nr * ROWE + kb));
                ldm_x4(bl[nfp], smem_addr(Bl + nr * ROWE + kb));
            }
            // ---- 3 passes of 16 independent MMAs (no same-acc chains) ----
#pragma unroll
            for (int mf = 0; mf < 2; mf++)
#pragma unroll
                for (int nfp = 0; nfp < 4; nfp++)
#pragma unroll
                    for (int j = 0; j < 2; j++)
                        mma16816(acc[mf][nfp * 2 + j], ah[mf],
                                 bh[nfp][2 * j], bh[nfp][2 * j + 1]);
#pragma unroll
            for (int mf = 0; mf < 2; mf++)
#pragma unroll
                for (int nfp = 0; nfp < 4; nfp++)
#pragma unroll
                    for (int j = 0; j < 2; j++)
                        mma16816(acc[mf][nfp * 2 + j], ah[mf],
                                 bl[nfp][2 * j], bl[nfp][2 * j + 1]);
#pragma unroll
            for (int mf = 0; mf < 2; mf++)
#pragma unroll
                for (int nfp = 0; nfp < 4; nfp++)
#pragma unroll
                    for (int j = 0; j < 2; j++)
                        mma16816(acc[mf][nfp * 2 + j], al[mf],
                                 bh[nfp][2 * j], bh[nfp][2 * j + 1]);
        }
        __syncthreads();
    }

    // ---- epilogue ----
#pragma unroll
    for (int mf = 0; mf < 2; mf++) {
        const int r0 = bm + warpM * 32 + mf * 16 + (lane >> 2);
#pragma unroll
        for (int nf = 0; nf < 8; nf++) {
            const int cc = bn + warpN * 64 + nf * 8 + (lane & 3) * 2;
            float* p = Z + (size_t)r0 * FIVED + cc;
            if (r0 < M) {
                p[0] = acc[mf][nf][0];
                p[1] = acc[mf][nf][1];
            }
            if (r0 + 8 < M) {
                float* q = p + 8 * FIVED;
                q[0] = acc[mf][nf][2];
                q[1] = acc[mf][nf][3];
            }
        }
    }
}

// ---------------------------------------------------------------------------
// Pointwise merge cell (+ bf16 hi/lo mirror of h)
// ---------------------------------------------------------------------------
__global__ void pw_merge(const float* __restrict__ Z, const float* __restrict__ b,
                         const float* __restrict__ prevC,
                         float* __restrict__ curH, float* __restrict__ curC,
                         __nv_bfloat16* __restrict__ curHhi,
                         __nv_bfloat16* __restrict__ curHlo)
{
    const int m = blockIdx.x;
    const int j = threadIdx.x;
    const float* z = Z + (size_t)m * FIVED;
    float gi = z[j] + b[j];
    float go = z[256 + j] + b[256 + j];
    float gu = z[512 + j] + b[512 + j];
    float gfl = z[768 + j] + b[768 + j];
    float gfr = z[1024 + j] + b[1024 + j];
    float cl = prevC[(size_t)(2 * m) * DDIM + j];
    float cr = prevC[(size_t)(2 * m + 1) * DDIM + j];
    float c = sigf(gi) * tanhf(gu) + sigf(gfl) * cl + sigf(gfr) * cr;
    float h = sigf(go) * tanhf(c);
    curH[(size_t)m * DDIM + j] = h;
    curC[(size_t)m * DDIM + j] = c;
    __nv_bfloat16 hh = __float2bfloat16(h);
    curHhi[(size_t)m * DDIM + j] = hh;
    curHlo[(size_t)m * DDIM + j] = __float2bfloat16(h - __bfloat162float(hh));
}

// ---------------------------------------------------------------------------
// Pointwise fenwick-step cell: z = zL (per-step) + zN (precomputed node) + b
// ---------------------------------------------------------------------------
__global__ void pw_sum(const float* __restrict__ ZL, const float* __restrict__ ZNk,
                       const float* __restrict__ b,
                       const float* __restrict__ nodeH, const float* __restrict__ nodeC,
                       float* __restrict__ out,
                       __nv_bfloat16* __restrict__ stHhi,
                       __nv_bfloat16* __restrict__ stHlo, int k)
{
    const int m = blockIdx.x;
    const int j = threadIdx.x;
    const int mask = (1 << k) - 1;
    const int a = m >> k;
    const int r = m & mask;
    const int t = (a << (k + 1)) | (1 << k) | r;
    const int row = t - 1;
    const int idx = (t >> k) - 1;

    float h, c;
    if (r == 0) {
        h = nodeH[(size_t)idx * DDIM + j];
        c = nodeC[(size_t)idx * DDIM + j];
    } else {
        const float* zl = ZL + (size_t)m * FIVED;
        const float* zn = ZNk + (size_t)idx * FIVED;
        float gi = zl[j] + zn[j] + b[j];
        float go = zl[256 + j] + zn[256 + j] + b[256 + j];
        float gu = zl[512 + j] + zn[512 + j] + b[512 + j];
        float gfl = zl[768 + j] + zn[768 + j] + b[768 + j];
        float gfr = zl[1024 + j] + zn[1024 + j] + b[1024 + j];
        float cl = out[(size_t)row * 512 + 256 + j];
        float cr = nodeC[(size_t)idx * DDIM + j];
        c = sigf(gi) * tanhf(gu) + sigf(gfl) * cl + sigf(gfr) * cr;
        h = sigf(go) * tanhf(c);
    }
    out[(size_t)row * 512 + j] = h;
    out[(size_t)row * 512 + 256 + j] = c;
    __nv_bfloat16 hh = __float2bfloat16(h);
    stHhi[(size_t)row * DDIM + j] = hh;
    stHlo[(size_t)row * DDIM + j] = __float2bfloat16(h - __bfloat162float(hh));
}

static inline int lev_off(int k) { return NTOT - (NTOT >> (k - 1)); }

extern "C" void kernel_launch(void* const* d_in, const int* in_sizes, int n_in,
                              void* d_out, int out_size)
{
    const float* h_bot = (const float*)d_in[0];
    const float* c_bot = (const float*)d_in[1];
    const float* W_merge = (const float*)d_in[2];
    const float* b_merge = (const float*)d_in[3];
    const float* W_sum = (const float*)d_in[4];
    const float* b_sum = (const float*)d_in[5];
    float* out = (float*)d_out;

    float *levH, *levC, *Z, *ZN;
    __nv_bfloat16 *WtHiM, *WtLoM, *WtHiS, *WtLoS;
    __nv_bfloat16 *botHhi, *botHlo, *levHhi, *levHlo, *stHhi, *stHlo;
    cudaGetSymbolAddress((void**)&levH, g_levH);
    cudaGetSymbolAddress((void**)&levC, g_levC);
    cudaGetSymbolAddress((void**)&Z, g_Z);
    cudaGetSymbolAddress((void**)&ZN, g_ZN);
    cudaGetSymbolAddress((void**)&WtHiM, g_WtHiM);
    cudaGetSymbolAddress((void**)&WtLoM, g_WtLoM);
    cudaGetSymbolAddress((void**)&WtHiS, g_WtHiS);
    cudaGetSymbolAddress((void**)&WtLoS, g_WtLoS);
    cudaGetSymbolAddress((void**)&botHhi, g_botHhi);
    cudaGetSymbolAddress((void**)&botHlo, g_botHlo);
    cudaGetSymbolAddress((void**)&levHhi, g_levHhi);
    cudaGetSymbolAddress((void**)&levHlo, g_levHlo);
    cudaGetSymbolAddress((void**)&stHhi, g_stHhi);
    cudaGetSymbolAddress((void**)&stHlo, g_stHlo);

    cudaFuncSetAttribute(mma_gemm, cudaFuncAttributeMaxDynamicSharedMemorySize, SMEM_TOTAL);

    transpose_w<<<dim3(FIVED / 32, KDIM / 32), dim3(32, 8)>>>(W_merge, WtHiM, WtLoM);
    transpose_w<<<dim3(FIVED / 32, KDIM / 32), dim3(32, 8)>>>(W_sum, WtHiS, WtLoS);
    split_bot<<<NTOT, 256>>>(h_bot, botHhi, botHlo);

    // ---- Phase 1: build levels 1..15 ----
    for (int k = 1; k <= 15; k++) {
        int Mrows = NTOT >> k;
        const __nv_bfloat16* pHhi = (k == 1) ? botHhi : (levHhi + (size_t)lev_off(k - 1) * DDIM);
        const __nv_bfloat16* pHlo = (k == 1) ? botHlo : (levHlo + (size_t)lev_off(k - 1) * DDIM);
        const float* prevC = (k == 1) ? c_bot : (levC + (size_t)lev_off(k - 1) * DDIM);
        float* curH = levH + (size_t)lev_off(k) * DDIM;
        float* curC = levC + (size_t)lev_off(k) * DDIM;
        __nv_bfloat16* cHhi = levHhi + (size_t)lev_off(k) * DDIM;
        __nv_bfloat16* cHlo = levHlo + (size_t)lev_off(k) * DDIM;

        dim3 grid(FIVED / 128, (Mrows + 127) / 128);
        mma_gemm<<<grid, 256, SMEM_TOTAL>>>(pHhi, pHlo, DDIM, WtHiM, WtLoM, 0,
                                            Z, Mrows, 0, 0, 16);
        pw_merge<<<Mrows, 256>>>(Z, b_merge, prevC, curH, curC, cHhi, cHlo);
    }

    // ---- Precompute node-half gates for ALL tree nodes (K=256, W cols 256:512) ----
    {
        dim3 grid(FIVED / 128, (NTOT - 1 + 127) / 128);
        mma_gemm<<<grid, 256, SMEM_TOTAL>>>(levHhi, levHlo, DDIM, WtHiS, WtLoS, 256,
                                            ZN, NTOT - 1, 2, 0, 8);
    }

    // ---- Phase 2: fenwick prefix combine ----
    pw_sum<<<NTOT / 2, 256>>>(Z, ZN, b_sum, h_bot, c_bot, out, stHhi, stHlo, 0);

    for (int k = 1; k <= 14; k++) {
        const float* nodeH = levH + (size_t)lev_off(k) * DDIM;
        const float* nodeC = levC + (size_t)lev_off(k) * DDIM;
        const float* ZNk = ZN + (size_t)lev_off(k) * FIVED;
        dim3 grid(FIVED / 128, (NTOT / 2 + 127) / 128);
        mma_gemm<<<grid, 256, SMEM_TOTAL>>>(stHhi, stHlo, DDIM, WtHiS, WtLoS, 0,
                                            Z, NTOT / 2, 1, k, 8);
        pw_sum<<<NTOT / 2, 256>>>(Z, ZNk, b_sum, nodeH, nodeC, out, stHhi, stHlo, k);
    }

    {
        const float* nodeH = levH + (size_t)lev_off(15) * DDIM;
        const float* nodeC = levC + (size_t)lev_off(15) * DDIM;
        pw_sum<<<1, 256>>>(Z, ZN, b_sum, nodeH, nodeC, out, stHhi, stHlo, 15);
    }
}

// round 15
// speedup vs baseline: 2.2641x; 1.1919x over previous
#include <cuda_runtime.h>
#include <cuda_bf16.h>
#include <cstdint>

#define NTOT 32768
#define DDIM 256
#define KDIM 512
#define FIVED 1280

// ---------------- device scratch ----------------
__device__ float g_levH[(NTOT - 1) * DDIM];
__device__ float g_levC[(NTOT - 1) * DDIM];
__device__ float g_Z[16384 * FIVED];       // phase-2 scratch (main stream)
__device__ float g_Z1[16384 * FIVED];      // phase-1 scratch (side stream)
__device__ float g_ZN[(NTOT - 1) * FIVED]; // precomputed node-half gate preact
__device__ __nv_bfloat16 g_WtHiM[FIVED * KDIM];
__device__ __nv_bfloat16 g_WtLoM[FIVED * KDIM];
__device__ __nv_bfloat16 g_WtHiS[FIVED * KDIM];
__device__ __nv_bfloat16 g_WtLoS[FIVED * KDIM];
__device__ __nv_bfloat16 g_botHhi[NTOT * DDIM];
__device__ __nv_bfloat16 g_botHlo[NTOT * DDIM];
__device__ __nv_bfloat16 g_levHhi[(NTOT - 1) * DDIM];
__device__ __nv_bfloat16 g_levHlo[(NTOT - 1) * DDIM];
__device__ __nv_bfloat16 g_stHhi[NTOT * DDIM];
__device__ __nv_bfloat16 g_stHlo[NTOT * DDIM];

__device__ __forceinline__ float sigf(float x) { return 1.0f / (1.0f + __expf(-x)); }

// ---------------------------------------------------------------------------
// Weight transpose + bf16 hi/lo split: W[512,1280] -> WtHi/WtLo[1280,512]
// ---------------------------------------------------------------------------
__global__ void transpose_w(const float* __restrict__ W,
                            __nv_bfloat16* __restrict__ WtHi,
                            __nv_bfloat16* __restrict__ WtLo) {
    __shared__ float t[32][33];
    int bx = blockIdx.x * 32;   // n
    int by = blockIdx.y * 32;   // k
    int x = threadIdx.x, y = threadIdx.y;
#pragma unroll
    for (int i = 0; i < 32; i += 8)
        t[y + i][x] = W[(size_t)(by + y + i) * FIVED + bx + x];
    __syncthreads();
#pragma unroll
    for (int i = 0; i < 32; i += 8) {
        float v = t[x][y + i];
        __nv_bfloat16 hi = __float2bfloat16(v);
        __nv_bfloat16 lo = __float2bfloat16(v - __bfloat162float(hi));
        WtHi[(size_t)(bx + y + i) * KDIM + by + x] = hi;
        WtLo[(size_t)(bx + y + i) * KDIM + by + x] = lo;
    }
}

// h_bot -> bf16 hi/lo mirror
__global__ void split_bot(const float* __restrict__ h,
                          __nv_bfloat16* __restrict__ hhi,
                          __nv_bfloat16* __restrict__ hlo) {
    size_t i = (size_t)blockIdx.x * 256 + threadIdx.x;
    float v = h[i];
    __nv_bfloat16 a = __float2bfloat16(v);
    hhi[i] = a;
    hlo[i] = __float2bfloat16(v - __bfloat162float(a));
}

// ---------------- mma.sync helpers ----------------
__device__ __forceinline__ uint32_t smem_addr(const void* p) {
    return (uint32_t)__cvta_generic_to_shared(p);
}
__device__ __forceinline__ void ldm_x4(uint32_t r[4], uint32_t addr) {
    asm volatile("ldmatrix.sync.aligned.m8n8.x4.shared.b16 {%0,%1,%2,%3}, [%4];"
                 : "=r"(r[0]), "=r"(r[1]), "=r"(r[2]), "=r"(r[3]) : "r"(addr));
}
__device__ __forceinline__ void mma16816(float d[4], const uint32_t a[4],
                                         uint32_t b0, uint32_t b1) {
    asm volatile(
        "mma.sync.aligned.m16n8k16.row.col.f32.bf16.bf16.f32 "
        "{%0,%1,%2,%3}, {%4,%5,%6,%7}, {%8,%9}, {%0,%1,%2,%3};"
        : "+f"(d[0]), "+f"(d[1]), "+f"(d[2]), "+f"(d[3])
        : "r"(a[0]), "r"(a[1]), "r"(a[2]), "r"(a[3]), "r"(b0), "r"(b1));
}
__device__ __forceinline__ void cp16(void* dst, const void* src) {
    asm volatile("cp.async.cg.shared.global [%0], [%1], 16;"
                 :: "r"(smem_addr(dst)), "l"(src));
}
#define CP_COMMIT() asm volatile("cp.async.commit_group;" ::: "memory")
#define CP_WAIT(n)  asm volatile("cp.async.wait_group %0;" :: "n"(n) : "memory")

// SMEM row stride in bf16 elements (32 data + 8 pad = 80B rows)
#define ROWE 40
#define TSZ (128 * ROWE)
#define OFF_AH 0
#define OFF_AL TSZ
#define OFF_BH (2 * TSZ)
#define OFF_BL (3 * TSZ)
#define STAGE_SZ (4 * TSZ)
#define SMEM_TOTAL (2 * STAGE_SZ * 2)   // 80KB -> 2 CTAs/SM

// ---------------------------------------------------------------------------
// GEMM (bf16x3 mma.sync): Z[m, :] = Arow(m) @ Wt-slice
// mode 0 (merge, kChunks=16):  Arow = concat(LHi[2m], LHi[2m+1]) (K=512)
// mode 1 (fenwick packed, kChunks=8): p -> a = p/(2^k-1), r = p%(2^k-1)+1,
//         t = (a<<(k+1))|(1<<k)|r, Arow = L[t-1] (K=256). Rows with r==0
//         (copy path) are skipped entirely.
// mode 2 (identity, kChunks=8): Arow = L[m] (K=256)
// ---------------------------------------------------------------------------
__global__ void __launch_bounds__(256, 2) mma_gemm(
    const __nv_bfloat16* __restrict__ LHi, const __nv_bfloat16* __restrict__ LLo, int ls,
    const __nv_bfloat16* __restrict__ BHi, const __nv_bfloat16* __restrict__ BLo, int bOff,
    float* __restrict__ Z, int M, int mode, int k, int kChunks)
{
    extern __shared__ __align__(16) __nv_bfloat16 sm[];

    const int tid = threadIdx.x;
    const int wid = tid >> 5;
    const int lane = tid & 31;
    const int warpM = wid & 3;
    const int warpN = wid >> 2;
    const int bm = blockIdx.y * 128;
    const int bn = blockIdx.x * 128;

    // ---- load geometry: one row per thread-pair, 16 K-elems per thread ----
    const int row2 = tid >> 1;        // 0..127
    const int half = tid & 1;
    int g = bm + row2;
    if (g >= M) g = 0;
    int lr, rr;
    const int mask = (1 << k) - 1;    // group size for packed mode
    if (mode == 0) { lr = 2 * g; rr = 2 * g + 1; }
    else if (mode == 1) {
        int a = g / mask;
        int r = g - a * mask + 1;     // 1..mask
        int t = (a << (k + 1)) | (1 << k) | r;
        lr = t - 1;
        rr = lr;
    } else { lr = g; rr = g; }
    const __nv_bfloat16* LHr = LHi + (size_t)lr * ls + half * 16;
    const __nv_bfloat16* LLr = LLo + (size_t)lr * ls + half * 16;
    const __nv_bfloat16* RHr = LHi + (size_t)rr * ls + half * 16;
    const __nv_bfloat16* RLr = LLo + (size_t)rr * ls + half * 16;
    const size_t bRow = (size_t)(bn + row2) * KDIM + bOff + half * 16;
    const int dstOff = row2 * ROWE + half * 16;

    // ---- ldmatrix source coords ----
    const int aRowL = warpM * 32 + (lane & 15);
    const int aKL = (lane >> 4) << 3;
    const int bRowL = warpN * 64 + ((lane >> 4) << 3) + (lane & 7);
    const int bKL = ((lane >> 3) & 1) << 3;

    float acc[2][8][4];
#pragma unroll
    for (int mf = 0; mf < 2; mf++)
#pragma unroll
        for (int nf = 0; nf < 8; nf++)
#pragma unroll
            for (int j = 0; j < 4; j++) acc[mf][nf][j] = 0.0f;

    auto issue = [&](int c, int s) {
        const int k0 = c * 32;
        __nv_bfloat16* st = sm + s * STAGE_SZ;
        const __nv_bfloat16* ah;
        const __nv_bfloat16* al;
        if (k0 < 256) { ah = LHr + k0; al = LLr + k0; }
        else          { ah = RHr + (k0 - 256); al = RLr + (k0 - 256); }
        cp16(st + OFF_AH + dstOff, ah);
        cp16(st + OFF_AH + dstOff + 8, ah + 8);
        cp16(st + OFF_AL + dstOff, al);
        cp16(st + OFF_AL + dstOff + 8, al + 8);
        const __nv_bfloat16* bh = BHi + bRow + k0;
        const __nv_bfloat16* bl = BLo + bRow + k0;
        cp16(st + OFF_BH + dstOff, bh);
        cp16(st + OFF_BH + dstOff + 8, bh + 8);
        cp16(st + OFF_BL + dstOff, bl);
        cp16(st + OFF_BL + dstOff + 8, bl + 8);
    };

    issue(0, 0);
    CP_COMMIT();

#pragma unroll 1
    for (int c = 0; c < kChunks; c++) {
        if (c + 1 < kChunks) {
            issue(c + 1, (c + 1) & 1);
            CP_COMMIT();
            CP_WAIT(1);
        } else {
            CP_WAIT(0);
        }
        __syncthreads();

        const __nv_bfloat16* st = sm + (c & 1) * STAGE_SZ;
        const __nv_bfloat16* Ah = st + OFF_AH;
        const __nv_bfloat16* Al = st + OFF_AL;
        const __nv_bfloat16* Bh = st + OFF_BH;
        const __nv_bfloat16* Bl = st + OFF_BL;

#pragma unroll
        for (int kk = 0; kk < 32; kk += 16) {
            uint32_t ah[2][4], al[2][4];
#pragma unroll
            for (int mf = 0; mf < 2; mf++) {
                const int r = aRowL + mf * 16;
                const int kb = kk + aKL;
                ldm_x4(ah[mf], smem_addr(Ah + r * ROWE + kb));
                ldm_x4(al[mf], smem_addr(Al + r * ROWE + kb));
            }
            uint32_t bh[4][4], bl[4][4];
#pragma unroll
            for (int nfp = 0; nfp < 4; nfp++) {
                const int nr = bRowL + nfp * 16;
                const int kb = kk + bKL;
                ldm_x4(bh[nfp], smem_addr(Bh + nr * ROWE + kb));
                ldm_x4(bl[nfp], smem_addr(Bl + nr * ROWE + kb));
            }
            // 3 passes of 16 independent MMAs
#pragma unroll
            for (int mf = 0; mf < 2; mf++)
#pragma unroll
                for (int nfp = 0; nfp < 4; nfp++)
#pragma unroll
                    for (int j = 0; j < 2; j++)
                        mma16816(acc[mf][nfp * 2 + j], ah[mf],
                                 bh[nfp][2 * j], bh[nfp][2 * j + 1]);
#pragma unroll
            for (int mf = 0; mf < 2; mf++)
#pragma unroll
                for (int nfp = 0; nfp < 4; nfp++)
#pragma unroll
                    for (int j = 0; j < 2; j++)
                        mma16816(acc[mf][nfp * 2 + j], ah[mf],
                                 bl[nfp][2 * j], bl[nfp][2 * j + 1]);
#pragma unroll
            for (int mf = 0; mf < 2; mf++)
#pragma unroll
                for (int nfp = 0; nfp < 4; nfp++)
#pragma unroll
                    for (int j = 0; j < 2; j++)
                        mma16816(acc[mf][nfp * 2 + j], al[mf],
                                 bh[nfp][2 * j], bh[nfp][2 * j + 1]);
        }
        __syncthreads();
    }

    // ---- epilogue ----
#pragma unroll
    for (int mf = 0; mf < 2; mf++) {
        const int r0 = bm + warpM * 32 + mf * 16 + (lane >> 2);
#pragma unroll
        for (int nf = 0; nf < 8; nf++) {
            const int cc = bn + warpN * 64 + nf * 8 + (lane & 3) * 2;
            float* p = Z + (size_t)r0 * FIVED + cc;
            if (r0 < M) {
                p[0] = acc[mf][nf][0];
                p[1] = acc[mf][nf][1];
            }
            if (r0 + 8 < M) {
                float* q = p + 8 * FIVED;
                q[0] = acc[mf][nf][2];
                q[1] = acc[mf][nf][3];
            }
        }
    }
}

// ---------------------------------------------------------------------------
// Pointwise merge cell (+ bf16 hi/lo mirror of h)
// ---------------------------------------------------------------------------
__global__ void pw_merge(const float* __restrict__ Z, const float* __restrict__ b,
                         const float* __restrict__ prevC,
                         float* __restrict__ curH, float* __restrict__ curC,
                         __nv_bfloat16* __restrict__ curHhi,
                         __nv_bfloat16* __restrict__ curHlo)
{
    const int m = blockIdx.x;
    const int j = threadIdx.x;
    const float* z = Z + (size_t)m * FIVED;
    float gi = z[j] + b[j];
    float go = z[256 + j] + b[256 + j];
    float gu = z[512 + j] + b[512 + j];
    float gfl = z[768 + j] + b[768 + j];
    float gfr = z[1024 + j] + b[1024 + j];
    float cl = prevC[(size_t)(2 * m) * DDIM + j];
    float cr = prevC[(size_t)(2 * m + 1) * DDIM + j];
    float c = sigf(gi) * tanhf(gu) + sigf(gfl) * cl + sigf(gfr) * cr;
    float h = sigf(go) * tanhf(c);
    curH[(size_t)m * DDIM + j] = h;
    curC[(size_t)m * DDIM + j] = c;
    __nv_bfloat16 hh = __float2bfloat16(h);
    curHhi[(size_t)m * DDIM + j] = hh;
    curHlo[(size_t)m * DDIM + j] = __float2bfloat16(h - __bfloat162float(hh));
}

// ---------------------------------------------------------------------------
// Pointwise fenwick-step cell: z = zL[packed p] + zN[node] + b
// ---------------------------------------------------------------------------
__global__ void pw_sum(const float* __restrict__ ZL, const float* __restrict__ ZNk,
                       const float* __restrict__ b,
                       const float* __restrict__ nodeH, const float* __restrict__ nodeC,
                       float* __restrict__ out,
                       __nv_bfloat16* __restrict__ stHhi,
                       __nv_bfloat16* __restrict__ stHlo, int k)
{
    const int m = blockIdx.x;
    const int j = threadIdx.x;
    const int mask = (1 << k) - 1;
    const int a = m >> k;
    const int r = m & mask;
    const int t = (a << (k + 1)) | (1 << k) | r;
    const int row = t - 1;
    const int idx = (t >> k) - 1;

    float h, c;
    if (r == 0) {
        h = nodeH[(size_t)idx * DDIM + j];
        c = nodeC[(size_t)idx * DDIM + j];
    } else {
        const int p = a * mask + (r - 1);     // packed Z row
        const float* zl = ZL + (size_t)p * FIVED;
        const float* zn = ZNk + (size_t)idx * FIVED;
        float gi = zl[j] + zn[j] + b[j];
        float go = zl[256 + j] + zn[256 + j] + b[256 + j];
        float gu = zl[512 + j] + zn[512 + j] + b[512 + j];
        float gfl = zl[768 + j] + zn[768 + j] + b[768 + j];
        float gfr = zl[1024 + j] + zn[1024 + j] + b[1024 + j];
        float cl = out[(size_t)row * 512 + 256 + j];
        float cr = nodeC[(size_t)idx * DDIM + j];
        c = sigf(gi) * tanhf(gu) + sigf(gfl) * cl + sigf(gfr) * cr;
        h = sigf(go) * tanhf(c);
    }
    out[(size_t)row * 512 + j] = h;
    out[(size_t)row * 512 + 256 + j] = c;
    __nv_bfloat16 hh = __float2bfloat16(h);
    stHhi[(size_t)row * DDIM + j] = hh;
    stHlo[(size_t)row * DDIM + j] = __float2bfloat16(h - __bfloat162float(hh));
}

static inline int lev_off(int k) { return NTOT - (NTOT >> (k - 1)); }

extern "C" void kernel_launch(void* const* d_in, const int* in_sizes, int n_in,
                              void* d_out, int out_size)
{
    const float* h_bot = (const float*)d_in[0];
    const float* c_bot = (const float*)d_in[1];
    const float* W_merge = (const float*)d_in[2];
    const float* b_merge = (const float*)d_in[3];
    const float* W_sum = (const float*)d_in[4];
    const float* b_sum = (const float*)d_in[5];
    float* out = (float*)d_out;

    float *levH, *levC, *Z, *Z1, *ZN;
    __nv_bfloat16 *WtHiM, *WtLoM, *WtHiS, *WtLoS;
    __nv_bfloat16 *botHhi, *botHlo, *levHhi, *levHlo, *stHhi, *stHlo;
    cudaGetSymbolAddress((void**)&levH, g_levH);
    cudaGetSymbolAddress((void**)&levC, g_levC);
    cudaGetSymbolAddress((void**)&Z, g_Z);
    cudaGetSymbolAddress((void**)&Z1, g_Z1);
    cudaGetSymbolAddress((void**)&ZN, g_ZN);
    cudaGetSymbolAddress((void**)&WtHiM, g_WtHiM);
    cudaGetSymbolAddress((void**)&WtLoM, g_WtLoM);
    cudaGetSymbolAddress((void**)&WtHiS, g_WtHiS);
    cudaGetSymbolAddress((void**)&WtLoS, g_WtLoS);
    cudaGetSymbolAddress((void**)&botHhi, g_botHhi);
    cudaGetSymbolAddress((void**)&botHlo, g_botHlo);
    cudaGetSymbolAddress((void**)&levHhi, g_levHhi);
    cudaGetSymbolAddress((void**)&levHlo, g_levHlo);
    cudaGetSymbolAddress((void**)&stHhi, g_stHhi);
    cudaGetSymbolAddress((void**)&stHlo, g_stHlo);

    cudaFuncSetAttribute(mma_gemm, cudaFuncAttributeMaxDynamicSharedMemorySize, SMEM_TOTAL);

    // one-time host objects (created during the correctness run, reused in capture)
    static cudaStream_t s1 = nullptr;
    static cudaEvent_t evFork;
    static cudaEvent_t evLvl[16];
    if (!s1) {
        cudaStreamCreateWithFlags(&s1, cudaStreamNonBlocking);
        cudaEventCreateWithFlags(&evFork, cudaEventDisableTiming);
        for (int i = 0; i < 16; i++)
            cudaEventCreateWithFlags(&evLvl[i], cudaEventDisableTiming);
    }

    // ---- shared prep on main (capture-origin) stream ----
    transpose_w<<<dim3(FIVED / 32, KDIM / 32), dim3(32, 8)>>>(W_merge, WtHiM, WtLoM);
    transpose_w<<<dim3(FIVED / 32, KDIM / 32), dim3(32, 8)>>>(W_sum, WtHiS, WtLoS);
    split_bot<<<NTOT, 256>>>(h_bot, botHhi, botHlo);
    cudaEventRecord(evFork, 0);
    cudaStreamWaitEvent(s1, evFork, 0);

    // ---- side stream s1: phase-1 level build + per-level ZN ----
    for (int k = 1; k <= 15; k++) {
        int Mrows = NTOT >> k;
        const __nv_bfloat16* pHhi = (k == 1) ? botHhi : (levHhi + (size_t)lev_off(k - 1) * DDIM);
        const __nv_bfloat16* pHlo = (k == 1) ? botHlo : (levHlo + (size_t)lev_off(k - 1) * DDIM);
        const float* prevC = (k == 1) ? c_bot : (levC + (size_t)lev_off(k - 1) * DDIM);
        float* curH = levH + (size_t)lev_off(k) * DDIM;
        float* curC = levC + (size_t)lev_off(k) * DDIM;
        __nv_bfloat16* cHhi = levHhi + (size_t)lev_off(k) * DDIM;
        __nv_bfloat16* cHlo = levHlo + (size_t)lev_off(k) * DDIM;

        dim3 grid(FIVED / 128, (Mrows + 127) / 128);
        mma_gemm<<<grid, 256, SMEM_TOTAL, s1>>>(pHhi, pHlo, DDIM, WtHiM, WtLoM, 0,
                                                Z1, Mrows, 0, 0, 16);
        pw_merge<<<Mrows, 256, 0, s1>>>(Z1, b_merge, prevC, curH, curC, cHhi, cHlo);
        if (k <= 14) {
            // node-half gates for this level's nodes (K=256, W_sum cols 256:512)
            dim3 gz(FIVED / 128, (Mrows + 127) / 128);
            mma_gemm<<<gz, 256, SMEM_TOTAL, s1>>>(cHhi, cHlo, DDIM, WtHiS, WtLoS, 256,
                                                  ZN + (size_t)lev_off(k) * FIVED,
                                                  Mrows, 2, 0, 8);
        }
        cudaEventRecord(evLvl[k], s1);
    }

    // ---- main stream: fenwick prefix combine ----
    pw_sum<<<NTOT / 2, 256>>>(Z, ZN, b_sum, h_bot, c_bot, out, stHhi, stHlo, 0);

    for (int k = 1; k <= 14; k++) {
        cudaStreamWaitEvent(0, evLvl[k], 0);
        const float* nodeH = levH + (size_t)lev_off(k) * DDIM;
        const float* nodeC = levC + (size_t)lev_off(k) * DDIM;
        const float* ZNk = ZN + (size_t)lev_off(k) * FIVED;
        int Mk = (NTOT / 2) - ((NTOT / 2) >> k);   // packed: rows with r != 0
        dim3 grid(FIVED / 128, (Mk + 127) / 128);
        mma_gemm<<<grid, 256, SMEM_TOTAL>>>(stHhi, stHlo, DDIM, WtHiS, WtLoS, 0,
                                            Z, Mk, 1, k, 8);
        pw_sum<<<NTOT / 2, 256>>>(Z, ZNk, b_sum, nodeH, nodeC, out, stHhi, stHlo, k);
    }

    {
        cudaStreamWaitEvent(0, evLvl[15], 0);
        const float* nodeH = levH + (size_t)lev_off(15) * DDIM;
        const float* nodeC = levC + (size_t)lev_off(15) * DDIM;
        pw_sum<<<1, 256>>>(Z, ZN, b_sum, nodeH, nodeC, out, stHhi, stHlo, 15);
    }
}

// round 16
// speedup vs baseline: 2.4683x; 1.0902x over previous
#include <cuda_runtime.h>
#include <cuda_bf16.h>
#include <cuda_fp16.h>
#include <cstdint>

#define NTOT 32768
#define DDIM 256
#define KDIM 512
#define FIVED 1280

// ---------------- device scratch ----------------
__device__ float g_levH[(NTOT - 1) * DDIM];
__device__ float g_levC[(NTOT - 1) * DDIM];
__device__ __half g_Z[16384 * FIVED];       // phase-2 scratch (fp16, main stream)
__device__ float  g_Z1[16384 * FIVED];      // phase-1 scratch (fp32, side stream)
__device__ __half g_ZN[(NTOT - 1) * FIVED]; // node-half gate preact (fp16)
__device__ __nv_bfloat16 g_WtHiM[FIVED * KDIM];
__device__ __nv_bfloat16 g_WtLoM[FIVED * KDIM];
__device__ __nv_bfloat16 g_WtHiS[FIVED * KDIM];
__device__ __nv_bfloat16 g_WtLoS[FIVED * KDIM];
__device__ __nv_bfloat16 g_botHhi[NTOT * DDIM];
__device__ __nv_bfloat16 g_botHlo[NTOT * DDIM];
__device__ __nv_bfloat16 g_levHhi[(NTOT - 1) * DDIM];
__device__ __nv_bfloat16 g_levHlo[(NTOT - 1) * DDIM];
__device__ __nv_bfloat16 g_stHhi[NTOT * DDIM];
__device__ __nv_bfloat16 g_stHlo[NTOT * DDIM];

__device__ __forceinline__ float sigf(float x) { return 1.0f / (1.0f + __expf(-x)); }

// ---------------------------------------------------------------------------
// Weight transpose + bf16 hi/lo split: W[512,1280] -> WtHi/WtLo[1280,512]
// ---------------------------------------------------------------------------
__global__ void transpose_w(const float* __restrict__ W,
                            __nv_bfloat16* __restrict__ WtHi,
                            __nv_bfloat16* __restrict__ WtLo) {
    __shared__ float t[32][33];
    int bx = blockIdx.x * 32;   // n
    int by = blockIdx.y * 32;   // k
    int x = threadIdx.x, y = threadIdx.y;
#pragma unroll
    for (int i = 0; i < 32; i += 8)
        t[y + i][x] = W[(size_t)(by + y + i) * FIVED + bx + x];
    __syncthreads();
#pragma unroll
    for (int i = 0; i < 32; i += 8) {
        float v = t[x][y + i];
        __nv_bfloat16 hi = __float2bfloat16(v);
        __nv_bfloat16 lo = __float2bfloat16(v - __bfloat162float(hi));
        WtHi[(size_t)(bx + y + i) * KDIM + by + x] = hi;
        WtLo[(size_t)(bx + y + i) * KDIM + by + x] = lo;
    }
}

// h_bot -> bf16 hi/lo mirror
__global__ void split_bot(const float* __restrict__ h,
                          __nv_bfloat16* __restrict__ hhi,
                          __nv_bfloat16* __restrict__ hlo) {
    size_t i = (size_t)blockIdx.x * 256 + threadIdx.x;
    float v = h[i];
    __nv_bfloat16 a = __float2bfloat16(v);
    hhi[i] = a;
    hlo[i] = __float2bfloat16(v - __bfloat162float(a));
}

// ---------------- mma.sync helpers ----------------
__device__ __forceinline__ uint32_t smem_addr(const void* p) {
    return (uint32_t)__cvta_generic_to_shared(p);
}
__device__ __forceinline__ void ldm_x4(uint32_t r[4], uint32_t addr) {
    asm volatile("ldmatrix.sync.aligned.m8n8.x4.shared.b16 {%0,%1,%2,%3}, [%4];"
                 : "=r"(r[0]), "=r"(r[1]), "=r"(r[2]), "=r"(r[3]) : "r"(addr));
}
__device__ __forceinline__ void mma16816(float d[4], const uint32_t a[4],
                                         uint32_t b0, uint32_t b1) {
    asm volatile(
        "mma.sync.aligned.m16n8k16.row.col.f32.bf16.bf16.f32 "
        "{%0,%1,%2,%3}, {%4,%5,%6,%7}, {%8,%9}, {%0,%1,%2,%3};"
        : "+f"(d[0]), "+f"(d[1]), "+f"(d[2]), "+f"(d[3])
        : "r"(a[0]), "r"(a[1]), "r"(a[2]), "r"(a[3]), "r"(b0), "r"(b1));
}
__device__ __forceinline__ void cp16(void* dst, const void* src) {
    asm volatile("cp.async.cg.shared.global [%0], [%1], 16;"
                 :: "r"(smem_addr(dst)), "l"(src));
}
#define CP_COMMIT() asm volatile("cp.async.commit_group;" ::: "memory")
#define CP_WAIT(n)  asm volatile("cp.async.wait_group %0;" :: "n"(n) : "memory")

// SMEM row stride in bf16 elements (32 data + 8 pad = 80B rows)
#define ROWE 40
#define TSZ (128 * ROWE)
#define OFF_AH 0
#define OFF_AL TSZ
#define OFF_BH (2 * TSZ)
#define OFF_BL (3 * TSZ)
#define STAGE_SZ (4 * TSZ)
#define SMEM_TOTAL (2 * STAGE_SZ * 2)   // 80KB -> 2 CTAs/SM

// ---------------------------------------------------------------------------
// GEMM (bf16x3 mma.sync), OutT in {float, __half}:
// mode 0 (merge, kChunks=16):  Arow = concat(LHi[2m], LHi[2m+1]) (K=512)
// mode 1 (fenwick packed, kChunks=8): p -> a = p/(2^k-1), r = p%(2^k-1)+1,
//         t = (a<<(k+1))|(1<<k)|r, Arow = L[t-1] (K=256); r==0 rows skipped.
// mode 2 (identity, kChunks=8): Arow = L[m] (K=256)
// ---------------------------------------------------------------------------
template <typename OutT>
__global__ void __launch_bounds__(256, 2) mma_gemm(
    const __nv_bfloat16* __restrict__ LHi, const __nv_bfloat16* __restrict__ LLo, int ls,
    const __nv_bfloat16* __restrict__ BHi, const __nv_bfloat16* __restrict__ BLo, int bOff,
    OutT* __restrict__ Z, int M, int mode, int k, int kChunks)
{
    extern __shared__ __align__(16) __nv_bfloat16 sm[];

    const int tid = threadIdx.x;
    const int wid = tid >> 5;
    const int lane = tid & 31;
    const int warpM = wid & 3;
    const int warpN = wid >> 2;
    const int bm = blockIdx.y * 128;
    const int bn = blockIdx.x * 128;

    // ---- load geometry: one row per thread-pair, 16 K-elems per thread ----
    const int row2 = tid >> 1;        // 0..127
    const int half = tid & 1;
    int g = bm + row2;
    if (g >= M) g = 0;
    int lr, rr;
    const int mask = (1 << k) - 1;
    if (mode == 0) { lr = 2 * g; rr = 2 * g + 1; }
    else if (mode == 1) {
        int a = g / mask;
        int r = g - a * mask + 1;     // 1..mask
        int t = (a << (k + 1)) | (1 << k) | r;
        lr = t - 1;
        rr = lr;
    } else { lr = g; rr = g; }
    const __nv_bfloat16* LHr = LHi + (size_t)lr * ls + half * 16;
    const __nv_bfloat16* LLr = LLo + (size_t)lr * ls + half * 16;
    const __nv_bfloat16* RHr = LHi + (size_t)rr * ls + half * 16;
    const __nv_bfloat16* RLr = LLo + (size_t)rr * ls + half * 16;
    const size_t bRow = (size_t)(bn + row2) * KDIM + bOff + half * 16;
    const int dstOff = row2 * ROWE + half * 16;

    // ---- ldmatrix source coords ----
    const int aRowL = warpM * 32 + (lane & 15);
    const int aKL = (lane >> 4) << 3;
    const int bRowL = warpN * 64 + ((lane >> 4) << 3) + (lane & 7);
    const int bKL = ((lane >> 3) & 1) << 3;

    float acc[2][8][4];
#pragma unroll
    for (int mf = 0; mf < 2; mf++)
#pragma unroll
        for (int nf = 0; nf < 8; nf++)
#pragma unroll
            for (int j = 0; j < 4; j++) acc[mf][nf][j] = 0.0f;

    auto issue = [&](int c, int s) {
        const int k0 = c * 32;
        __nv_bfloat16* st = sm + s * STAGE_SZ;
        const __nv_bfloat16* ah;
        const __nv_bfloat16* al;
        if (k0 < 256) { ah = LHr + k0; al = LLr + k0; }
        else          { ah = RHr + (k0 - 256); al = RLr + (k0 - 256); }
        cp16(st + OFF_AH + dstOff, ah);
        cp16(st + OFF_AH + dstOff + 8, ah + 8);
        cp16(st + OFF_AL + dstOff, al);
        cp16(st + OFF_AL + dstOff + 8, al + 8);
        const __nv_bfloat16* bh = BHi + bRow + k0;
        const __nv_bfloat16* bl = BLo + bRow + k0;
        cp16(st + OFF_BH + dstOff, bh);
        cp16(st + OFF_BH + dstOff + 8, bh + 8);
        cp16(st + OFF_BL + dstOff, bl);
        cp16(st + OFF_BL + dstOff + 8, bl + 8);
    };

    issue(0, 0);
    CP_COMMIT();

#pragma unroll 1
    for (int c = 0; c < kChunks; c++) {
        if (c + 1 < kChunks) {
            issue(c + 1, (c + 1) & 1);
            CP_COMMIT();
            CP_WAIT(1);
        } else {
            CP_WAIT(0);
        }
        __syncthreads();

        const __nv_bfloat16* st = sm + (c & 1) * STAGE_SZ;
        const __nv_bfloat16* Ah = st + OFF_AH;
        const __nv_bfloat16* Al = st + OFF_AL;
        const __nv_bfloat16* Bh = st + OFF_BH;
        const __nv_bfloat16* Bl = st + OFF_BL;

#pragma unroll
        for (int kk = 0; kk < 32; kk += 16) {
            uint32_t ah[2][4], al[2][4];
#pragma unroll
            for (int mf = 0; mf < 2; mf++) {
                const int r = aRowL + mf * 16;
                const int kb = kk + aKL;
                ldm_x4(ah[mf], smem_addr(Ah + r * ROWE + kb));
                ldm_x4(al[mf], smem_addr(Al + r * ROWE + kb));
            }
            uint32_t bh[4][4], bl[4][4];
#pragma unroll
            for (int nfp = 0; nfp < 4; nfp++) {
                const int nr = bRowL + nfp * 16;
                const int kb = kk + bKL;
                ldm_x4(bh[nfp], smem_addr(Bh + nr * ROWE + kb));
                ldm_x4(bl[nfp], smem_addr(Bl + nr * ROWE + kb));
            }
            // 3 passes of 16 independent MMAs
#pragma unroll
            for (int mf = 0; mf < 2; mf++)
#pragma unroll
                for (int nfp = 0; nfp < 4; nfp++)
#pragma unroll
                    for (int j = 0; j < 2; j++)
                        mma16816(acc[mf][nfp * 2 + j], ah[mf],
                                 bh[nfp][2 * j], bh[nfp][2 * j + 1]);
#pragma unroll
            for (int mf = 0; mf < 2; mf++)
#pragma unroll
                for (int nfp = 0; nfp < 4; nfp++)
#pragma unroll
                    for (int j = 0; j < 2; j++)
                        mma16816(acc[mf][nfp * 2 + j], ah[mf],
                                 bl[nfp][2 * j], bl[nfp][2 * j + 1]);
#pragma unroll
            for (int mf = 0; mf < 2; mf++)
#pragma unroll
                for (int nfp = 0; nfp < 4; nfp++)
#pragma unroll
                    for (int j = 0; j < 2; j++)
                        mma16816(acc[mf][nfp * 2 + j], al[mf],
                                 bh[nfp][2 * j], bh[nfp][2 * j + 1]);
        }
        __syncthreads();
    }

    // ---- epilogue ----
#pragma unroll
    for (int mf = 0; mf < 2; mf++) {
        const int r0 = bm + warpM * 32 + mf * 16 + (lane >> 2);
#pragma unroll
        for (int nf = 0; nf < 8; nf++) {
            const int cc = bn + warpN * 64 + nf * 8 + (lane & 3) * 2;
            if (r0 < M) {
                OutT* p = Z + (size_t)r0 * FIVED + cc;
                if constexpr (sizeof(OutT) == 2) {
                    *(__half2*)p = __floats2half2_rn(acc[mf][nf][0], acc[mf][nf][1]);
                } else {
                    p[0] = acc[mf][nf][0];
                    p[1] = acc[mf][nf][1];
                }
            }
            if (r0 + 8 < M) {
                OutT* q = Z + (size_t)(r0 + 8) * FIVED + cc;
                if constexpr (sizeof(OutT) == 2) {
                    *(__half2*)q = __floats2half2_rn(acc[mf][nf][2], acc[mf][nf][3]);
                } else {
                    q[0] = acc[mf][nf][2];
                    q[1] = acc[mf][nf][3];
                }
            }
        }
    }
}

// ---------------------------------------------------------------------------
// Pointwise merge cell (fp32 Z1; + bf16 hi/lo mirror of h)
// ---------------------------------------------------------------------------
__global__ void pw_merge(const float* __restrict__ Z, const float* __restrict__ b,
                         const float* __restrict__ prevC,
                         float* __restrict__ curH, float* __restrict__ curC,
                         __nv_bfloat16* __restrict__ curHhi,
                         __nv_bfloat16* __restrict__ curHlo)
{
    const int m = blockIdx.x;
    const int j = threadIdx.x;
    const float* z = Z + (size_t)m * FIVED;
    float gi = z[j] + b[j];
    float go = z[256 + j] + b[256 + j];
    float gu = z[512 + j] + b[512 + j];
    float gfl = z[768 + j] + b[768 + j];
    float gfr = z[1024 + j] + b[1024 + j];
    float cl = prevC[(size_t)(2 * m) * DDIM + j];
    float cr = prevC[(size_t)(2 * m + 1) * DDIM + j];
    float c = sigf(gi) * tanhf(gu) + sigf(gfl) * cl + sigf(gfr) * cr;
    float h = sigf(go) * tanhf(c);
    curH[(size_t)m * DDIM + j] = h;
    curC[(size_t)m * DDIM + j] = c;
    __nv_bfloat16 hh = __float2bfloat16(h);
    curHhi[(size_t)m * DDIM + j] = hh;
    curHlo[(size_t)m * DDIM + j] = __float2bfloat16(h - __bfloat162float(hh));
}

// ---------------------------------------------------------------------------
// Pointwise fenwick-step cell: z = zL[packed p] (fp16) + zN[node] (fp16) + b
// ---------------------------------------------------------------------------
__global__ void pw_sum(const __half* __restrict__ ZL, const __half* __restrict__ ZNk,
                       const float* __restrict__ b,
                       const float* __restrict__ nodeH, const float* __restrict__ nodeC,
                       float* __restrict__ out,
                       __nv_bfloat16* __restrict__ stHhi,
                       __nv_bfloat16* __restrict__ stHlo, int k)
{
    const int m = blockIdx.x;
    const int j = threadIdx.x;
    const int mask = (1 << k) - 1;
    const int a = m >> k;
    const int r = m & mask;
    const int t = (a << (k + 1)) | (1 << k) | r;
    const int row = t - 1;
    const int idx = (t >> k) - 1;

    float h, c;
    if (r == 0) {
        h = nodeH[(size_t)idx * DDIM + j];
        c = nodeC[(size_t)idx * DDIM + j];
    } else {
        const int p = a * mask + (r - 1);     // packed Z row
        const __half* zl = ZL + (size_t)p * FIVED;
        const __half* zn = ZNk + (size_t)idx * FIVED;
        float gi = __half2float(zl[j]) + __half2float(zn[j]) + b[j];
        float go = __half2float(zl[256 + j]) + __half2float(zn[256 + j]) + b[256 + j];
        float gu = __half2float(zl[512 + j]) + __half2float(zn[512 + j]) + b[512 + j];
        float gfl = __half2float(zl[768 + j]) + __half2float(zn[768 + j]) + b[768 + j];
        float gfr = __half2float(zl[1024 + j]) + __half2float(zn[1024 + j]) + b[1024 + j];
        float cl = out[(size_t)row * 512 + 256 + j];
        float cr = nodeC[(size_t)idx * DDIM + j];
        c = sigf(gi) * tanhf(gu) + sigf(gfl) * cl + sigf(gfr) * cr;
        h = sigf(go) * tanhf(c);
    }
    out[(size_t)row * 512 + j] = h;
    out[(size_t)row * 512 + 256 + j] = c;
    __nv_bfloat16 hh = __float2bfloat16(h);
    stHhi[(size_t)row * DDIM + j] = hh;
    stHlo[(size_t)row * DDIM + j] = __float2bfloat16(h - __bfloat162float(hh));
}

static inline int lev_off(int k) { return NTOT - (NTOT >> (k - 1)); }

extern "C" void kernel_launch(void* const* d_in, const int* in_sizes, int n_in,
                              void* d_out, int out_size)
{
    const float* h_bot = (const float*)d_in[0];
    const float* c_bot = (const float*)d_in[1];
    const float* W_merge = (const float*)d_in[2];
    const float* b_merge = (const float*)d_in[3];
    const float* W_sum = (const float*)d_in[4];
    const float* b_sum = (const float*)d_in[5];
    float* out = (float*)d_out;

    float *levH, *levC, *Z1;
    __half *Z, *ZN;
    __nv_bfloat16 *WtHiM, *WtLoM, *WtHiS, *WtLoS;
    __nv_bfloat16 *botHhi, *botHlo, *levHhi, *levHlo, *stHhi, *stHlo;
    cudaGetSymbolAddress((void**)&levH, g_levH);
    cudaGetSymbolAddress((void**)&levC, g_levC);
    cudaGetSymbolAddress((void**)&Z, g_Z);
    cudaGetSymbolAddress((void**)&Z1, g_Z1);
    cudaGetSymbolAddress((void**)&ZN, g_ZN);
    cudaGetSymbolAddress((void**)&WtHiM, g_WtHiM);
    cudaGetSymbolAddress((void**)&WtLoM, g_WtLoM);
    cudaGetSymbolAddress((void**)&WtHiS, g_WtHiS);
    cudaGetSymbolAddress((void**)&WtLoS, g_WtLoS);
    cudaGetSymbolAddress((void**)&botHhi, g_botHhi);
    cudaGetSymbolAddress((void**)&botHlo, g_botHlo);
    cudaGetSymbolAddress((void**)&levHhi, g_levHhi);
    cudaGetSymbolAddress((void**)&levHlo, g_levHlo);
    cudaGetSymbolAddress((void**)&stHhi, g_stHhi);
    cudaGetSymbolAddress((void**)&stHlo, g_stHlo);

    cudaFuncSetAttribute(mma_gemm<float>, cudaFuncAttributeMaxDynamicSharedMemorySize, SMEM_TOTAL);
    cudaFuncSetAttribute(mma_gemm<__half>, cudaFuncAttributeMaxDynamicSharedMemorySize, SMEM_TOTAL);

    // one-time host objects (created during the correctness run, reused in capture)
    static cudaStream_t s1 = nullptr;
    static cudaEvent_t evFork;
    static cudaEvent_t evLvl[16];
    if (!s1) {
        cudaStreamCreateWithFlags(&s1, cudaStreamNonBlocking);
        cudaEventCreateWithFlags(&evFork, cudaEventDisableTiming);
        for (int i = 0; i < 16; i++)
            cudaEventCreateWithFlags(&evLvl[i], cudaEventDisableTiming);
    }

    // ---- shared prep on main (capture-origin) stream ----
    transpose_w<<<dim3(FIVED / 32, KDIM / 32), dim3(32, 8)>>>(W_merge, WtHiM, WtLoM);
    transpose_w<<<dim3(FIVED / 32, KDIM / 32), dim3(32, 8)>>>(W_sum, WtHiS, WtLoS);
    split_bot<<<NTOT, 256>>>(h_bot, botHhi, botHlo);
    cudaEventRecord(evFork, 0);
    cudaStreamWaitEvent(s1, evFork, 0);

    // ---- side stream s1: phase-1 level build + per-level ZN ----
    for (int k = 1; k <= 15; k++) {
        int Mrows = NTOT >> k;
        const __nv_bfloat16* pHhi = (k == 1) ? botHhi : (levHhi + (size_t)lev_off(k - 1) * DDIM);
        const __nv_bfloat16* pHlo = (k == 1) ? botHlo : (levHlo + (size_t)lev_off(k - 1) * DDIM);
        const float* prevC = (k == 1) ? c_bot : (levC + (size_t)lev_off(k - 1) * DDIM);
        float* curH = levH + (size_t)lev_off(k) * DDIM;
        float* curC = levC + (size_t)lev_off(k) * DDIM;
        __nv_bfloat16* cHhi = levHhi + (size_t)lev_off(k) * DDIM;
        __nv_bfloat16* cHlo = levHlo + (size_t)lev_off(k) * DDIM;

        dim3 grid(FIVED / 128, (Mrows + 127) / 128);
        mma_gemm<float><<<grid, 256, SMEM_TOTAL, s1>>>(pHhi, pHlo, DDIM, WtHiM, WtLoM, 0,
                                                       Z1, Mrows, 0, 0, 16);
        pw_merge<<<Mrows, 256, 0, s1>>>(Z1, b_merge, prevC, curH, curC, cHhi, cHlo);
        if (k <= 14) {
            dim3 gz(FIVED / 128, (Mrows + 127) / 128);
            mma_gemm<__half><<<gz, 256, SMEM_TOTAL, s1>>>(cHhi, cHlo, DDIM, WtHiS, WtLoS, 256,
                                                          ZN + (size_t)lev_off(k) * FIVED,
                                                          Mrows, 2, 0, 8);
        }
        cudaEventRecord(evLvl[k], s1);
    }

    // ---- main stream: fenwick prefix combine ----
    pw_sum<<<NTOT / 2, 256>>>(Z, ZN, b_sum, h_bot, c_bot, out, stHhi, stHlo, 0);

    for (int k = 1; k <= 14; k++) {
        cudaStreamWaitEvent(0, evLvl[k], 0);
        const float* nodeH = levH + (size_t)lev_off(k) * DDIM;
        const float* nodeC = levC + (size_t)lev_off(k) * DDIM;
        const __half* ZNk = ZN + (size_t)lev_off(k) * FIVED;
        int Mk = (NTOT / 2) - ((NTOT / 2) >> k);   // packed: rows with r != 0
        dim3 grid(FIVED / 128, (Mk + 127) / 128);
        mma_gemm<__half><<<grid, 256, SMEM_TOTAL>>>(stHhi, stHlo, DDIM, WtHiS, WtLoS, 0,
                                                    Z, Mk, 1, k, 8);
        pw_sum<<<NTOT / 2, 256>>>(Z, ZNk, b_sum, nodeH, nodeC, out, stHhi, stHlo, k);
    }

    {
        cudaStreamWaitEvent(0, evLvl[15], 0);
        const float* nodeH = levH + (size_t)lev_off(15) * DDIM;
        const float* nodeC = levC + (size_t)lev_off(15) * DDIM;
        pw_sum<<<1, 256>>>(Z, ZN, b_sum, nodeH, nodeC, out, stHhi, stHlo, 15);
    }
}